// round 2
// baseline (speedup 1.0000x reference)
#include <cuda_runtime.h>
#include <cuda_bf16.h>
#include <math.h>

#define T 2048
#define H 1024
#define NH 16
#define NKV 4
#define HD 64
#define E 32
#define TOPK 4
#define IM 384
#define QKVW 1536   // (NH + 2*NKV) * HD
#define NSLOT (T*TOPK)

// ---------------- scratch (device globals; no allocation allowed) ------------
__device__ float g_res1[T*H];
__device__ float g_x[T*H];
__device__ float g_qkv[T*QKVW];
__device__ float g_attno[T*H];
__device__ float g_h[T*H];
__device__ float g_x2[T*H];
__device__ float g_gu[NSLOT*2*IM];
__device__ float g_act[NSLOT*IM];
__device__ float g_y[NSLOT*H];
__device__ float g_gus[T*2*IM];
__device__ float g_acts[T*IM];
__device__ float g_shared[T*H];
__device__ int   g_ids[T*TOPK];
__device__ float g_w[T*TOPK];
__device__ int   g_cnt[E];
__device__ int   g_off[E];
__device__ int   g_fill[E];
__device__ int   g_slot2tok[NSLOT];
__device__ int   g_tokslot[T*TOPK];

// -------- fused residual-add + rmsnorm (H=1024, 256 thr, float4) ------------
__global__ void add_rmsnorm_kernel(const float* __restrict__ a, const float* __restrict__ b,
                                   float* __restrict__ res, const float* __restrict__ w,
                                   float* __restrict__ y) {
    int t = blockIdx.x, tid = threadIdx.x;
    __shared__ float red[256];
    const float4* a4 = (const float4*)(a + (size_t)t * H);
    const float4* b4 = (const float4*)(b + (size_t)t * H);
    float4 va = a4[tid], vb = b4[tid];
    float4 v = make_float4(va.x + vb.x, va.y + vb.y, va.z + vb.z, va.w + vb.w);
    ((float4*)(res + (size_t)t * H))[tid] = v;
    float s = v.x*v.x + v.y*v.y + v.z*v.z + v.w*v.w;
    red[tid] = s; __syncthreads();
    for (int o = 128; o; o >>= 1) { if (tid < o) red[tid] += red[tid+o]; __syncthreads(); }
    float inv = rsqrtf(red[0] / (float)H + 1e-5f);
    float4 wv = ((const float4*)w)[tid];
    float4 o4 = make_float4(v.x*inv*wv.x, v.y*inv*wv.y, v.z*inv*wv.z, v.w*inv*wv.w);
    ((float4*)(y + (size_t)t * H))[tid] = o4;
}

__global__ void silu_mul_kernel(const float* __restrict__ gu, float* __restrict__ out, int total) {
    int i = blockIdx.x * blockDim.x + threadIdx.x;
    if (i >= total) return;
    int r = i / IM, c = i % IM;
    float g = gu[r*2*IM + c], u = gu[r*2*IM + IM + c];
    out[i] = g * (1.f / (1.f + expf(-g))) * u;
}

// ---------------- SGEMM: C[M,N] = A[M,K] @ B[K,N], row-major, vectorized ------
// 64x64 tile, 16-deep K, 4x4 microtile, float4 smem traffic.
__global__ void sgemm(const float* __restrict__ A, const float* __restrict__ B,
                      float* __restrict__ C, int M, int N, int K) {
    __shared__ float As[16][68];   // [kk][m]
    __shared__ float Bs[16][68];   // [kk][n]
    int bm = blockIdx.y * 64, bn = blockIdx.x * 64;
    int tid = threadIdx.x, tx = tid & 15, ty = tid >> 4;
    int lm = tid >> 2, lq = tid & 3;   // A: row lm, quarter lq
    int lk = tid >> 4, ln = tid & 15;  // B: k-row lk, float4 col ln
    float acc[4][4] = {};
    for (int k0 = 0; k0 < K; k0 += 16) {
        float4 av = *(const float4*)&A[(size_t)(bm + lm) * K + k0 + lq*4];
        As[lq*4+0][lm] = av.x; As[lq*4+1][lm] = av.y;
        As[lq*4+2][lm] = av.z; As[lq*4+3][lm] = av.w;
        *(float4*)&Bs[lk][ln*4] = *(const float4*)&B[(size_t)(k0 + lk) * N + bn + ln*4];
        __syncthreads();
        #pragma unroll
        for (int kk = 0; kk < 16; kk++) {
            float4 a4 = *(const float4*)&As[kk][ty*4];
            float4 b4 = *(const float4*)&Bs[kk][tx*4];
            acc[0][0] += a4.x*b4.x; acc[0][1] += a4.x*b4.y; acc[0][2] += a4.x*b4.z; acc[0][3] += a4.x*b4.w;
            acc[1][0] += a4.y*b4.x; acc[1][1] += a4.y*b4.y; acc[1][2] += a4.y*b4.z; acc[1][3] += a4.y*b4.w;
            acc[2][0] += a4.z*b4.x; acc[2][1] += a4.z*b4.y; acc[2][2] += a4.z*b4.z; acc[2][3] += a4.z*b4.w;
            acc[3][0] += a4.w*b4.x; acc[3][1] += a4.w*b4.y; acc[3][2] += a4.w*b4.z; acc[3][3] += a4.w*b4.w;
        }
        __syncthreads();
    }
    #pragma unroll
    for (int i = 0; i < 4; i++)
        *(float4*)&C[(size_t)(bm + ty*4 + i) * N + bn + tx*4] =
            make_float4(acc[i][0], acc[i][1], acc[i][2], acc[i][3]);
}

// ------------- gathered per-expert SGEMM (MoE) -------------------------------
__global__ void sgemm_moe(const float* __restrict__ X, int ldx,
                          const float* __restrict__ W, long wstride,
                          float* __restrict__ C, int N, int K, int gatherX) {
    int e = blockIdx.z;
    int cnt = g_cnt[e];
    int bm = blockIdx.y * 64;
    if (bm >= cnt) return;
    int base = g_off[e];
    __shared__ int rows[64];
    __shared__ float As[16][68];
    __shared__ float Bs[16][68];
    int tid = threadIdx.x, tx = tid & 15, ty = tid >> 4;
    int lm = tid >> 2, lq = tid & 3;
    int lk = tid >> 4, ln = tid & 15;
    int bn = blockIdx.x * 64;
    if (tid < 64) {
        int rr = bm + tid;
        rows[tid] = (rr < cnt) ? (gatherX ? g_slot2tok[base + rr] : base + rr) : -1;
    }
    __syncthreads();
    const float* B = W + (long)e * wstride;
    int arow = rows[lm];
    float acc[4][4] = {};
    for (int k0 = 0; k0 < K; k0 += 16) {
        float4 av = make_float4(0.f, 0.f, 0.f, 0.f);
        if (arow >= 0) av = *(const float4*)&X[(size_t)arow * ldx + k0 + lq*4];
        As[lq*4+0][lm] = av.x; As[lq*4+1][lm] = av.y;
        As[lq*4+2][lm] = av.z; As[lq*4+3][lm] = av.w;
        *(float4*)&Bs[lk][ln*4] = *(const float4*)&B[(size_t)(k0 + lk) * N + bn + ln*4];
        __syncthreads();
        #pragma unroll
        for (int kk = 0; kk < 16; kk++) {
            float4 a4 = *(const float4*)&As[kk][ty*4];
            float4 b4 = *(const float4*)&Bs[kk][tx*4];
            acc[0][0] += a4.x*b4.x; acc[0][1] += a4.x*b4.y; acc[0][2] += a4.x*b4.z; acc[0][3] += a4.x*b4.w;
            acc[1][0] += a4.y*b4.x; acc[1][1] += a4.y*b4.y; acc[1][2] += a4.y*b4.z; acc[1][3] += a4.y*b4.w;
            acc[2][0] += a4.z*b4.x; acc[2][1] += a4.z*b4.y; acc[2][2] += a4.z*b4.z; acc[2][3] += a4.z*b4.w;
            acc[3][0] += a4.w*b4.x; acc[3][1] += a4.w*b4.y; acc[3][2] += a4.w*b4.z; acc[3][3] += a4.w*b4.w;
        }
        __syncthreads();
    }
    #pragma unroll
    for (int i = 0; i < 4; i++) {
        int r = bm + ty*4 + i;
        if (r < cnt)
            *(float4*)&C[(size_t)(base + r) * N + bn + tx*4] =
                make_float4(acc[i][0], acc[i][1], acc[i][2], acc[i][3]);
    }
}

// ---------------- Q/K rmsnorm + RoPE (in place on g_qkv) ---------------------
__global__ void qknorm_rope_kernel(const float* __restrict__ qw, const float* __restrict__ kw,
                                   const int* __restrict__ pos) {
    int t = blockIdx.x, hh = blockIdx.y;
    float* v;
    const float* w;
    if (hh < NH) { v = g_qkv + (size_t)t*QKVW + hh*HD; w = qw; }
    else         { v = g_qkv + (size_t)t*QKVW + NH*HD + (hh-NH)*HD; w = kw; }
    int lane = threadIdx.x;
    float a = v[lane], b = v[lane + 32];
    float ss = a*a + b*b;
    #pragma unroll
    for (int o = 16; o; o >>= 1) ss += __shfl_xor_sync(0xffffffffu, ss, o);
    float inv = rsqrtf(ss / (float)HD + 1e-5f);
    a *= inv * w[lane]; b *= inv * w[lane + 32];
    __shared__ float sh[64];
    sh[lane] = a; sh[lane + 32] = b;
    __syncwarp();
    float p = (float)pos[t];
    if (lane < 16) {
        float invf = expf(-((float)lane / 16.f) * logf(10000.f));
        float ang = p * invf;
        float c = cosf(ang), s = sinf(ang);
        float x1 = sh[lane], x2 = sh[lane + 16];
        v[lane]      = x1*c - x2*s;
        v[lane + 16] = x1*s + x2*c;
    } else {
        v[lane + 16] = sh[lane + 16];
        v[lane + 32] = sh[lane + 32];
    }
}

// ---------------- flash attention (fp32, online softmax) ---------------------
// grid: (T/64, NH), block 256, dyn smem = 4*64*65*4 bytes
__global__ void attn_kernel(const int* __restrict__ positions) {
    extern __shared__ float sm[];
    float* Qs = sm;
    float* Ks = sm + 64*65;
    float* Vs = sm + 2*64*65;
    float* Ps = sm + 3*64*65;
    int qt = blockIdx.x, h = blockIdx.y;
    int q0 = qt * 64, kvh = h >> 2;
    int tid = threadIdx.x, tx = tid & 15, ty = tid >> 4;

    for (int i = tid; i < 64*64; i += 256) {
        int r = i >> 6, c = i & 63;
        Qs[r*65 + c] = g_qkv[(size_t)(q0 + r)*QKVW + h*HD + c];
    }
    int pq[4];
    #pragma unroll
    for (int i = 0; i < 4; i++) pq[i] = positions[q0 + ty*4 + i];
    float m[4], l[4], O[4][4];
    #pragma unroll
    for (int i = 0; i < 4; i++) {
        m[i] = -INFINITY; l[i] = 0.f;
        #pragma unroll
        for (int j = 0; j < 4; j++) O[i][j] = 0.f;
    }
    __syncthreads();

    for (int jt = 0; jt <= qt; jt++) {
        int k0 = jt * 64;
        for (int i = tid; i < 64*64; i += 256) {
            int r = i >> 6, c = i & 63;
            Ks[r*65 + c] = g_qkv[(size_t)(k0 + r)*QKVW + NH*HD + kvh*HD + c];
            Vs[r*65 + c] = g_qkv[(size_t)(k0 + r)*QKVW + (NH+NKV)*HD + kvh*HD + c];
        }
        __syncthreads();

        float s[4][4] = {};
        #pragma unroll 8
        for (int kk = 0; kk < 64; kk++) {
            float a[4], b[4];
            #pragma unroll
            for (int i = 0; i < 4; i++) a[i] = Qs[(ty*4 + i)*65 + kk];
            #pragma unroll
            for (int j = 0; j < 4; j++) b[j] = Ks[(tx*4 + j)*65 + kk];
            #pragma unroll
            for (int i = 0; i < 4; i++)
                #pragma unroll
                for (int j = 0; j < 4; j++) s[i][j] += a[i] * b[j];
        }
        int pk[4];
        #pragma unroll
        for (int j = 0; j < 4; j++) pk[j] = positions[k0 + tx*4 + j];
        #pragma unroll
        for (int i = 0; i < 4; i++)
            #pragma unroll
            for (int j = 0; j < 4; j++)
                s[i][j] = (pq[i] >= pk[j]) ? s[i][j] * 0.125f : -INFINITY;

        #pragma unroll
        for (int i = 0; i < 4; i++) {
            float mloc = s[i][0];
            #pragma unroll
            for (int j = 1; j < 4; j++) mloc = fmaxf(mloc, s[i][j]);
            #pragma unroll
            for (int o = 8; o; o >>= 1) mloc = fmaxf(mloc, __shfl_xor_sync(0xffffffffu, mloc, o));
            float mnew = fmaxf(m[i], mloc);
            float alpha = expf(m[i] - mnew);
            float ps = 0.f;
            #pragma unroll
            for (int j = 0; j < 4; j++) { float p = expf(s[i][j] - mnew); s[i][j] = p; ps += p; }
            #pragma unroll
            for (int o = 8; o; o >>= 1) ps += __shfl_xor_sync(0xffffffffu, ps, o);
            l[i] = l[i] * alpha + ps;
            m[i] = mnew;
            #pragma unroll
            for (int j = 0; j < 4; j++) O[i][j] *= alpha;
            #pragma unroll
            for (int j = 0; j < 4; j++) Ps[(ty*4 + i)*65 + tx*4 + j] = s[i][j];
        }
        __syncwarp();

        #pragma unroll 8
        for (int kk = 0; kk < 64; kk++) {
            float a[4], b[4];
            #pragma unroll
            for (int i = 0; i < 4; i++) a[i] = Ps[(ty*4 + i)*65 + kk];
            #pragma unroll
            for (int j = 0; j < 4; j++) b[j] = Vs[kk*65 + tx*4 + j];
            #pragma unroll
            for (int i = 0; i < 4; i++)
                #pragma unroll
                for (int j = 0; j < 4; j++) O[i][j] += a[i] * b[j];
        }
        __syncthreads();
    }
    #pragma unroll
    for (int i = 0; i < 4; i++)
        #pragma unroll
        for (int j = 0; j < 4; j++)
            g_attno[(size_t)(q0 + ty*4 + i)*H + h*HD + tx*4 + j] = O[i][j] / l[i];
}

// ---------------- router ------------------------------------------------------
__global__ void router_kernel(const float* __restrict__ Wg, const float* __restrict__ bias) {
    int t = blockIdx.x, tx = threadIdx.x;
    __shared__ float xs[H];
    __shared__ float scr[E], sfc[E];
    for (int hh = tx; hh < H; hh += 32) xs[hh] = g_x2[(size_t)t*H + hh];
    __syncthreads();
    float acc = 0.f;
    for (int hh = 0; hh < H; hh++) acc += xs[hh] * Wg[hh*E + tx];
    float sc = 1.f / (1.f + expf(-acc));
    scr[tx] = sc; sfc[tx] = sc + bias[tx];
    __syncthreads();
    if (tx == 0) {
        float gs[4];
        for (int g = 0; g < 4; g++) {
            float m1 = -INFINITY, m2 = -INFINITY;
            for (int j = 0; j < 8; j++) {
                float v = sfc[g*8 + j];
                if (v > m1) { m2 = m1; m1 = v; } else if (v > m2) m2 = v;
            }
            gs[g] = m1 + m2;
        }
        int g1 = 0;
        for (int g = 1; g < 4; g++) if (gs[g] > gs[g1]) g1 = g;
        int g2 = -1;
        for (int g = 0; g < 4; g++) { if (g == g1) continue; if (g2 < 0 || gs[g] > gs[g2]) g2 = g; }
        bool used[E];
        for (int e = 0; e < E; e++) used[e] = false;
        float wk[TOPK]; int idk[TOPK]; float wsum = 0.f;
        for (int k = 0; k < TOPK; k++) {
            int best = -1; float bv = -INFINITY;
            for (int e = 0; e < E; e++) {
                int g = e >> 3;
                if (g != g1 && g != g2) continue;
                if (used[e]) continue;
                if (sfc[e] > bv) { bv = sfc[e]; best = e; }
            }
            used[best] = true; idk[k] = best;
            wk[k] = scr[best]; wsum += wk[k];
        }
        for (int k = 0; k < TOPK; k++) {
            g_ids[t*TOPK + k] = idk[k];
            g_w[t*TOPK + k] = wk[k] / wsum;
            atomicAdd(&g_cnt[idk[k]], 1);
        }
    }
}

__global__ void zero_kernel() {
    int i = threadIdx.x;
    if (i < E) { g_cnt[i] = 0; g_fill[i] = 0; }
}

__global__ void scan_kernel() {
    if (threadIdx.x == 0) {
        int s = 0;
        for (int e = 0; e < E; e++) { g_off[e] = s; s += g_cnt[e]; }
    }
}

__global__ void scatter_kernel() {
    int t = blockIdx.x * blockDim.x + threadIdx.x;
    if (t >= T) return;
    for (int k = 0; k < TOPK; k++) {
        int e = g_ids[t*TOPK + k];
        int slot = g_off[e] + atomicAdd(&g_fill[e], 1);
        g_slot2tok[slot] = t;
        g_tokslot[t*TOPK + k] = slot;
    }
}

// ---------------- final combine: hidden = sum_k w*y_slot + shared ------------
__global__ void combine_kernel(float* __restrict__ out) {
    int t = blockIdx.x, tid = threadIdx.x;
    int s0 = g_tokslot[t*TOPK + 0], s1 = g_tokslot[t*TOPK + 1];
    int s2 = g_tokslot[t*TOPK + 2], s3 = g_tokslot[t*TOPK + 3];
    float w0 = g_w[t*TOPK + 0], w1 = g_w[t*TOPK + 1];
    float w2 = g_w[t*TOPK + 2], w3 = g_w[t*TOPK + 3];
    const float4* sh4 = (const float4*)(g_shared + (size_t)t*H);
    const float4* y0 = (const float4*)(g_y + (size_t)s0*H);
    const float4* y1 = (const float4*)(g_y + (size_t)s1*H);
    const float4* y2 = (const float4*)(g_y + (size_t)s2*H);
    const float4* y3 = (const float4*)(g_y + (size_t)s3*H);
    float4* o4 = (float4*)(out + (size_t)t*H);
    int c = tid;  // H/4 == 256 == blockDim
    float4 a = sh4[c], v0 = y0[c], v1 = y1[c], v2 = y2[c], v3 = y3[c];
    o4[c] = make_float4(
        a.x + w0*v0.x + w1*v1.x + w2*v2.x + w3*v3.x,
        a.y + w0*v0.y + w1*v1.y + w2*v2.y + w3*v3.y,
        a.z + w0*v0.z + w1*v1.z + w2*v2.z + w3*v3.z,
        a.w + w0*v0.w + w1*v1.w + w2*v2.w + w3*v3.w);
}

// ---------------- host orchestration -----------------------------------------
extern "C" void kernel_launch(void* const* d_in, const int* in_sizes, int n_in,
                              void* d_out, int out_size) {
    const float* hidden   = (const float*)d_in[0];
    const float* residual = (const float*)d_in[1];
    const float* in_ln_w  = (const float*)d_in[2];
    const float* post_ln_w= (const float*)d_in[3];
    const float* q_norm_w = (const float*)d_in[4];
    const float* k_norm_w = (const float*)d_in[5];
    const float* Wqkv     = (const float*)d_in[6];
    const float* Wo       = (const float*)d_in[7];
    const float* Wg       = (const float*)d_in[8];
    const float* gate_bias= (const float*)d_in[9];
    const float* Wgu      = (const float*)d_in[10];
    const float* Wd       = (const float*)d_in[11];
    const float* Wgu_sh   = (const float*)d_in[12];
    const float* Wd_sh    = (const float*)d_in[13];
    const int*   positions= (const int*)d_in[14];
    float* out = (float*)d_out;

    float *p_res1, *p_x, *p_qkv, *p_attno, *p_h, *p_x2, *p_gu, *p_act, *p_y,
          *p_gus, *p_acts, *p_shared;
    cudaGetSymbolAddress((void**)&p_res1,  g_res1);
    cudaGetSymbolAddress((void**)&p_x,     g_x);
    cudaGetSymbolAddress((void**)&p_qkv,   g_qkv);
    cudaGetSymbolAddress((void**)&p_attno, g_attno);
    cudaGetSymbolAddress((void**)&p_h,     g_h);
    cudaGetSymbolAddress((void**)&p_x2,    g_x2);
    cudaGetSymbolAddress((void**)&p_gu,    g_gu);
    cudaGetSymbolAddress((void**)&p_act,   g_act);
    cudaGetSymbolAddress((void**)&p_y,     g_y);
    cudaGetSymbolAddress((void**)&p_gus,   g_gus);
    cudaGetSymbolAddress((void**)&p_acts,  g_acts);
    cudaGetSymbolAddress((void**)&p_shared,g_shared);

    // 1. residual1 = hidden + residual ; x = rms(residual1) * in_ln_w
    add_rmsnorm_kernel<<<T, 256>>>(hidden, residual, p_res1, in_ln_w, p_x);

    // 2. qkv = x @ Wqkv
    sgemm<<<dim3(QKVW/64, T/64), 256>>>(p_x, Wqkv, p_qkv, T, QKVW, H);

    // 3. q/k rmsnorm + rope (in place)
    qknorm_rope_kernel<<<dim3(T, NH + NKV), 32>>>(q_norm_w, k_norm_w, positions);

    // 4. attention
    cudaFuncSetAttribute(attn_kernel, cudaFuncAttributeMaxDynamicSharedMemorySize, 4*64*65*4);
    attn_kernel<<<dim3(T/64, NH), 256, 4*64*65*4>>>(positions);

    // 5. h = attno @ Wo ; residual2 = h + residual1 -> out[T*H..] ; x2 = rms(residual2)*post_ln
    sgemm<<<dim3(H/64, T/64), 256>>>(p_attno, Wo, p_h, T, H, H);
    float* out_res = out + (size_t)T*H;
    add_rmsnorm_kernel<<<T, 256>>>(p_h, p_res1, out_res, post_ln_w, p_x2);

    // 6. router + dispatch
    zero_kernel<<<1, 32>>>();
    router_kernel<<<T, 32>>>(Wg, gate_bias);
    scan_kernel<<<1, 1>>>();
    scatter_kernel<<<(T + 255)/256, 256>>>();

    // 7. routed experts: gu -> act -> down
    sgemm_moe<<<dim3(2*IM/64, NSLOT/64, E), 256>>>(p_x2, H, Wgu, (long)H*2*IM, p_gu, 2*IM, H, 1);
    silu_mul_kernel<<<(NSLOT*IM + 255)/256, 256>>>(p_gu, p_act, NSLOT*IM);
    sgemm_moe<<<dim3(H/64, NSLOT/64, E), 256>>>(p_act, IM, Wd, (long)IM*H, p_y, H, IM, 0);

    // 8. shared expert
    sgemm<<<dim3(2*IM/64, T/64), 256>>>(p_x2, Wgu_sh, p_gus, T, 2*IM, H);
    silu_mul_kernel<<<(T*IM + 255)/256, 256>>>(p_gus, p_acts, T*IM);
    sgemm<<<dim3(H/64, T/64), 256>>>(p_acts, Wd_sh, p_shared, T, H, IM);

    // 9. combine -> out[0..T*H)
    combine_kernel<<<T, 256>>>(out);
}

// round 5
// speedup vs baseline: 1.2531x; 1.2531x over previous
#include <cuda_runtime.h>
#include <cuda_bf16.h>
#include <math.h>
#include <stdint.h>

#define T 2048
#define H 1024
#define NH 16
#define NKV 4
#define HD 64
#define E 32
#define TOPK 4
#define IM 384
#define QKVW 1536   // (NH + 2*NKV) * HD
#define NSLOT (T*TOPK)

typedef __nv_bfloat16 bf16;

// ---------------- scratch (device globals; no allocation allowed) ------------
__device__ float g_res1[T*H];
__device__ float g_qkv[T*QKVW];
__device__ float g_attno[T*H];
__device__ float g_h[T*H];
__device__ float g_x2[T*H];
__device__ float g_gu[NSLOT*2*IM];
__device__ float g_y[(size_t)NSLOT*H];
__device__ float g_gus[T*2*IM];
__device__ float g_shared[T*H];
__device__ int   g_ids[T*TOPK];
__device__ float g_w[T*TOPK];
__device__ int   g_cnt[E];
__device__ int   g_off[E];
__device__ int   g_fill[E];
__device__ int   g_slot2tok[NSLOT];
__device__ int   g_tokslot[T*TOPK];

// bf16 split activations
__device__ bf16 g_xhi[T*H],   g_xlo[T*H];
__device__ bf16 g_x2hi[T*H],  g_x2lo[T*H];
__device__ bf16 g_aohi[T*H],  g_aolo[T*H];
__device__ bf16 g_acthi[NSLOT*IM],  g_actlo[NSLOT*IM];
__device__ bf16 g_actshi[T*IM],     g_actslo[T*IM];
// bf16 split + transposed weights ([N,K] layout, per-expert contiguous)
__device__ bf16 g_wqkvhi[(size_t)QKVW*H], g_wqkvlo[(size_t)QKVW*H];
__device__ bf16 g_wohi[(size_t)H*H],      g_wolo[(size_t)H*H];
__device__ bf16 g_wguhi[(size_t)E*2*IM*H], g_wgulo[(size_t)E*2*IM*H];
__device__ bf16 g_wdhi[(size_t)E*H*IM],    g_wdlo[(size_t)E*H*IM];
__device__ bf16 g_wgushi[(size_t)2*IM*H],  g_wguslo[(size_t)2*IM*H];
__device__ bf16 g_wdshi[(size_t)H*IM],     g_wdslo[(size_t)H*IM];

__device__ __forceinline__ uint32_t smem_u32(const void* p) {
    uint32_t a;
    asm("{ .reg .u64 t; cvta.to.shared.u64 t, %1; cvt.u32.u64 %0, t; }" : "=r"(a) : "l"(p));
    return a;
}

#define CP8(s, g, sz) \
    asm volatile("cp.async.ca.shared.global [%0], [%1], 8, %2;" :: "r"(s), "l"(g), "r"(sz))
#define CP_COMMIT() asm volatile("cp.async.commit_group;" ::: "memory")
#define CP_WAIT1()  asm volatile("cp.async.wait_group 1;" ::: "memory")

#define MMA_BF16(c, a, b) \
    asm volatile("mma.sync.aligned.m16n8k16.row.col.f32.bf16.bf16.f32 " \
        "{%0,%1,%2,%3}, {%4,%5,%6,%7}, {%8,%9}, {%0,%1,%2,%3};" \
        : "+f"((c)[0]), "+f"((c)[1]), "+f"((c)[2]), "+f"((c)[3]) \
        : "r"((a)[0]), "r"((a)[1]), "r"((a)[2]), "r"((a)[3]), "r"((b)[0]), "r"((b)[1]))

// ======================= tensor-core GEMM (mma.sync) =========================
// C[M,N] = (Ahi+Alo)[M,K] @ (Bhi+Blo)^T with B stored [N,K] row-major.
// 3-term split: hi*hi + hi*lo + lo*hi accumulated into one f32 fragment set.
// CTA tile 128x128 (8 warps, warp tile 64x32). K chunks of 32, cp.async
// double buffer. Smem pitch 40 bf16 (80B) => conflict-free fragment LDS.
#define GP 40
#define TILE_B (128*GP*2)            // 10240 bytes per tile
#define OFF_ALO (1*TILE_B)
#define OFF_BHI (2*TILE_B)
#define OFF_BLO (3*TILE_B)
#define CHUNK_B (4*TILE_B)           // 40960
#define GSM_TOTAL (2*CHUNK_B)        // 81920

__global__ __launch_bounds__(256) void tc_gemm(
    const bf16* __restrict__ Ahi, const bf16* __restrict__ Alo,
    const bf16* __restrict__ Bhi, const bf16* __restrict__ Blo,
    float* __restrict__ C, int N, int K, int moe, int gather)
{
    extern __shared__ __align__(16) char dsm[];
    int tid = threadIdx.x;
    int warp = tid >> 5, lane = tid & 31;
    int wm = warp & 1, wn = warp >> 1;
    int g = lane >> 2, t2 = (lane & 3) * 2;
    int bn = blockIdx.x * 128;
    int bm = blockIdx.y * 128;

    int cnt = 0, basem = 0;
    const bf16* bh = Bhi; const bf16* bl = Blo;
    if (moe) {
        int e = blockIdx.z;
        cnt = g_cnt[e];
        if (bm >= cnt) return;
        basem = g_off[e];
        size_t ws = (size_t)N * K;
        bh += ws * (size_t)e; bl += ws * (size_t)e;
    }

    // global load mapping: each thread owns row r, 16-col half h
    int r = tid >> 1, h = tid & 1;
    long arow;
    uint32_t asz = 8;
    if (moe) {
        int rr = bm + r;
        if (rr < cnt) arow = gather ? (long)g_slot2tok[basem + rr] : (long)(basem + rr);
        else { arow = 0; asz = 0; }
    } else arow = bm + r;
    long brow = bn + r;

    uint32_t sbase = smem_u32(dsm);
    uint32_t srow = (uint32_t)(r * GP + h * 16) * 2;   // byte offset in tile

    auto prefetch = [&](int c, int b) {
        size_t ka = (size_t)c * 32 + h * 16;
        uint32_t sb = sbase + b * CHUNK_B + srow;
        const bf16* gah = Ahi + arow * K + ka;
        const bf16* gal = Alo + arow * K + ka;
        const bf16* gbh = bh + brow * K + ka;
        const bf16* gbl = bl + brow * K + ka;
        #pragma unroll
        for (int i = 0; i < 4; i++) {
            CP8(sb + i*8,           gah + i*4, asz);
            CP8(sb + OFF_ALO + i*8, gal + i*4, asz);
            CP8(sb + OFF_BHI + i*8, gbh + i*4, 8u);
            CP8(sb + OFF_BLO + i*8, gbl + i*4, 8u);
        }
    };

    float acc[4][4][4];
    #pragma unroll
    for (int mi = 0; mi < 4; mi++)
        #pragma unroll
        for (int ni = 0; ni < 4; ni++)
            #pragma unroll
            for (int q = 0; q < 4; q++) acc[mi][ni][q] = 0.f;

    int NC = K / 32;
    prefetch(0, 0);
    CP_COMMIT();

    for (int c = 0; c < NC; c++) {
        int b = c & 1;
        if (c + 1 < NC) prefetch(c + 1, b ^ 1);
        CP_COMMIT();
        CP_WAIT1();
        __syncthreads();

        const bf16* Ah = (const bf16*)(dsm + b * CHUNK_B);
        const bf16* Al = (const bf16*)(dsm + b * CHUNK_B + OFF_ALO);
        const bf16* Bh = (const bf16*)(dsm + b * CHUNK_B + OFF_BHI);
        const bf16* Bl = (const bf16*)(dsm + b * CHUNK_B + OFF_BLO);

        #pragma unroll
        for (int ks = 0; ks < 2; ks++) {
            int ko = ks * 16;
            uint32_t ah[4][4], al[4][4], bhf[4][2], blf[4][2];
            #pragma unroll
            for (int mi = 0; mi < 4; mi++) {
                int row = wm * 64 + mi * 16 + g;
                ah[mi][0] = *(const uint32_t*)&Ah[row * GP + ko + t2];
                ah[mi][1] = *(const uint32_t*)&Ah[(row + 8) * GP + ko + t2];
                ah[mi][2] = *(const uint32_t*)&Ah[row * GP + ko + t2 + 8];
                ah[mi][3] = *(const uint32_t*)&Ah[(row + 8) * GP + ko + t2 + 8];
                al[mi][0] = *(const uint32_t*)&Al[row * GP + ko + t2];
                al[mi][1] = *(const uint32_t*)&Al[(row + 8) * GP + ko + t2];
                al[mi][2] = *(const uint32_t*)&Al[row * GP + ko + t2 + 8];
                al[mi][3] = *(const uint32_t*)&Al[(row + 8) * GP + ko + t2 + 8];
            }
            #pragma unroll
            for (int ni = 0; ni < 4; ni++) {
                int nr = wn * 32 + ni * 8 + g;
                bhf[ni][0] = *(const uint32_t*)&Bh[nr * GP + ko + t2];
                bhf[ni][1] = *(const uint32_t*)&Bh[nr * GP + ko + t2 + 8];
                blf[ni][0] = *(const uint32_t*)&Bl[nr * GP + ko + t2];
                blf[ni][1] = *(const uint32_t*)&Bl[nr * GP + ko + t2 + 8];
            }
            #pragma unroll
            for (int mi = 0; mi < 4; mi++)
                #pragma unroll
                for (int ni = 0; ni < 4; ni++) {
                    MMA_BF16(acc[mi][ni], ah[mi], bhf[ni]);
                    MMA_BF16(acc[mi][ni], ah[mi], blf[ni]);
                    MMA_BF16(acc[mi][ni], al[mi], bhf[ni]);
                }
        }
        __syncthreads();
    }

    // epilogue
    #pragma unroll
    for (int mi = 0; mi < 4; mi++) {
        int lr0 = bm + wm * 64 + mi * 16 + g;
        int lr1 = lr0 + 8;
        bool v0 = moe ? (lr0 < cnt) : true;
        bool v1 = moe ? (lr1 < cnt) : true;
        size_t ro0 = ((size_t)(moe ? basem : 0) + lr0) * N;
        size_t ro1 = ((size_t)(moe ? basem : 0) + lr1) * N;
        #pragma unroll
        for (int ni = 0; ni < 4; ni++) {
            int col = bn + wn * 32 + ni * 8 + t2;
            if (v0) *(float2*)&C[ro0 + col] = make_float2(acc[mi][ni][0], acc[mi][ni][1]);
            if (v1) *(float2*)&C[ro1 + col] = make_float2(acc[mi][ni][2], acc[mi][ni][3]);
        }
    }
}

// ===================== conversion kernels ====================================
__global__ void split_kernel(const float* __restrict__ x, bf16* __restrict__ hi,
                             bf16* __restrict__ lo, int n) {
    int i = (blockIdx.x * blockDim.x + threadIdx.x) * 4;
    if (i >= n) return;
    float4 v = *(const float4*)(x + i);
    bf16 h0 = __float2bfloat16(v.x), h1 = __float2bfloat16(v.y);
    bf16 h2 = __float2bfloat16(v.z), h3 = __float2bfloat16(v.w);
    bf16 l0 = __float2bfloat16(v.x - __bfloat162float(h0));
    bf16 l1 = __float2bfloat16(v.y - __bfloat162float(h1));
    bf16 l2 = __float2bfloat16(v.z - __bfloat162float(h2));
    bf16 l3 = __float2bfloat16(v.w - __bfloat162float(h3));
    __nv_bfloat162* Hp = (__nv_bfloat162*)(hi + i);
    __nv_bfloat162* Lp = (__nv_bfloat162*)(lo + i);
    Hp[0] = __halves2bfloat162(h0, h1); Hp[1] = __halves2bfloat162(h2, h3);
    Lp[0] = __halves2bfloat162(l0, l1); Lp[1] = __halves2bfloat162(l2, l3);
}

// weight transpose + split: W[K,N] fp32 -> hi/lo [N,K] bf16 (batched over z)
__global__ void wsplitT(const float* __restrict__ W, bf16* __restrict__ hi,
                        bf16* __restrict__ lo, int K, int N) {
    size_t ws = (size_t)K * N * blockIdx.z;
    const float* Wp = W + ws;
    bf16* hp = hi + ws; bf16* lp = lo + ws;
    __shared__ float tl[32][33];
    int n0 = blockIdx.x * 32, k0 = blockIdx.y * 32;
    int tx = threadIdx.x, ty = threadIdx.y;
    #pragma unroll
    for (int j = 0; j < 4; j++) {
        int k = ty + j * 8;
        tl[k][tx] = Wp[(size_t)(k0 + k) * N + n0 + tx];
    }
    __syncthreads();
    #pragma unroll
    for (int j = 0; j < 4; j++) {
        int nl = ty + j * 8;
        float v = tl[tx][nl];
        bf16 h = __float2bfloat16(v);
        size_t o = (size_t)(n0 + nl) * K + k0 + tx;
        hp[o] = h;
        lp[o] = __float2bfloat16(v - __bfloat162float(h));
    }
}

// -------- fused residual-add + rmsnorm + split (H=1024, 256 thr) -------------
__global__ void add_rmsnorm_kernel(const float* __restrict__ a, const float* __restrict__ b,
                                   float* __restrict__ res, const float* __restrict__ w,
                                   float* __restrict__ y, bf16* __restrict__ yhi,
                                   bf16* __restrict__ ylo) {
    int t = blockIdx.x, tid = threadIdx.x;
    __shared__ float red[256];
    const float4* a4 = (const float4*)(a + (size_t)t * H);
    const float4* b4 = (const float4*)(b + (size_t)t * H);
    float4 va = a4[tid], vb = b4[tid];
    float4 v = make_float4(va.x + vb.x, va.y + vb.y, va.z + vb.z, va.w + vb.w);
    ((float4*)(res + (size_t)t * H))[tid] = v;
    float s = v.x*v.x + v.y*v.y + v.z*v.z + v.w*v.w;
    red[tid] = s; __syncthreads();
    for (int o = 128; o; o >>= 1) { if (tid < o) red[tid] += red[tid + o]; __syncthreads(); }
    float inv = rsqrtf(red[0] / (float)H + 1e-5f);
    float4 wv = ((const float4*)w)[tid];
    float4 o4 = make_float4(v.x*inv*wv.x, v.y*inv*wv.y, v.z*inv*wv.z, v.w*inv*wv.w);
    if (y) ((float4*)(y + (size_t)t * H))[tid] = o4;
    bf16 h0 = __float2bfloat16(o4.x), h1 = __float2bfloat16(o4.y);
    bf16 h2 = __float2bfloat16(o4.z), h3 = __float2bfloat16(o4.w);
    bf16 l0 = __float2bfloat16(o4.x - __bfloat162float(h0));
    bf16 l1 = __float2bfloat16(o4.y - __bfloat162float(h1));
    bf16 l2 = __float2bfloat16(o4.z - __bfloat162float(h2));
    bf16 l3 = __float2bfloat16(o4.w - __bfloat162float(h3));
    __nv_bfloat162* Hp = (__nv_bfloat162*)(yhi + (size_t)t * H) + tid * 2;
    __nv_bfloat162* Lp = (__nv_bfloat162*)(ylo + (size_t)t * H) + tid * 2;
    Hp[0] = __halves2bfloat162(h0, h1); Hp[1] = __halves2bfloat162(h2, h3);
    Lp[0] = __halves2bfloat162(l0, l1); Lp[1] = __halves2bfloat162(l2, l3);
}

// silu(gate)*up fused with bf16 split output
__global__ void silu_split(const float* __restrict__ gu, bf16* __restrict__ hi,
                           bf16* __restrict__ lo, int total) {
    int i = blockIdx.x * blockDim.x + threadIdx.x;
    if (i >= total) return;
    int r = i / IM, c = i % IM;
    float g = gu[(size_t)r*2*IM + c], u = gu[(size_t)r*2*IM + IM + c];
    float a = g * (1.f / (1.f + expf(-g))) * u;
    bf16 h = __float2bfloat16(a);
    hi[i] = h;
    lo[i] = __float2bfloat16(a - __bfloat162float(h));
}

// ---------------- Q/K rmsnorm + RoPE (in place on g_qkv) ---------------------
__global__ void qknorm_rope_kernel(const float* __restrict__ qw, const float* __restrict__ kw,
                                   const int* __restrict__ pos) {
    int t = blockIdx.x, hh = blockIdx.y;
    float* v;
    const float* w;
    if (hh < NH) { v = g_qkv + (size_t)t*QKVW + hh*HD; w = qw; }
    else         { v = g_qkv + (size_t)t*QKVW + NH*HD + (hh-NH)*HD; w = kw; }
    int lane = threadIdx.x;
    float a = v[lane], b = v[lane + 32];
    float ss = a*a + b*b;
    #pragma unroll
    for (int o = 16; o; o >>= 1) ss += __shfl_xor_sync(0xffffffffu, ss, o);
    float inv = rsqrtf(ss / (float)HD + 1e-5f);
    a *= inv * w[lane]; b *= inv * w[lane + 32];
    __shared__ float sh[64];
    sh[lane] = a; sh[lane + 32] = b;
    __syncwarp();
    float p = (float)pos[t];
    if (lane < 16) {
        float invf = expf(-((float)lane / 16.f) * logf(10000.f));
        float ang = p * invf;
        float c = cosf(ang), s = sinf(ang);
        float x1 = sh[lane], x2 = sh[lane + 16];
        v[lane]      = x1*c - x2*s;
        v[lane + 16] = x1*s + x2*c;
    } else {
        v[lane + 16] = sh[lane + 16];
        v[lane + 32] = sh[lane + 32];
    }
}

// ---------------- flash attention (fp32, online softmax) ---------------------
__global__ void attn_kernel(const int* __restrict__ positions) {
    extern __shared__ float sm[];
    float* Qs = sm;
    float* Ks = sm + 64*65;
    float* Vs = sm + 2*64*65;
    float* Ps = sm + 3*64*65;
    int qt = blockIdx.x, h = blockIdx.y;
    int q0 = qt * 64, kvh = h >> 2;
    int tid = threadIdx.x, tx = tid & 15, ty = tid >> 4;

    for (int i = tid; i < 64*64; i += 256) {
        int r = i >> 6, c = i & 63;
        Qs[r*65 + c] = g_qkv[(size_t)(q0 + r)*QKVW + h*HD + c];
    }
    int pq[4];
    #pragma unroll
    for (int i = 0; i < 4; i++) pq[i] = positions[q0 + ty*4 + i];
    float m[4], l[4], O[4][4];
    #pragma unroll
    for (int i = 0; i < 4; i++) {
        m[i] = -INFINITY; l[i] = 0.f;
        #pragma unroll
        for (int j = 0; j < 4; j++) O[i][j] = 0.f;
    }
    __syncthreads();

    for (int jt = 0; jt <= qt; jt++) {
        int k0 = jt * 64;
        for (int i = tid; i < 64*64; i += 256) {
            int r = i >> 6, c = i & 63;
            Ks[r*65 + c] = g_qkv[(size_t)(k0 + r)*QKVW + NH*HD + kvh*HD + c];
            Vs[r*65 + c] = g_qkv[(size_t)(k0 + r)*QKVW + (NH+NKV)*HD + kvh*HD + c];
        }
        __syncthreads();

        float s[4][4] = {};
        #pragma unroll 8
        for (int kk = 0; kk < 64; kk++) {
            float a[4], b[4];
            #pragma unroll
            for (int i = 0; i < 4; i++) a[i] = Qs[(ty*4 + i)*65 + kk];
            #pragma unroll
            for (int j = 0; j < 4; j++) b[j] = Ks[(tx*4 + j)*65 + kk];
            #pragma unroll
            for (int i = 0; i < 4; i++)
                #pragma unroll
                for (int j = 0; j < 4; j++) s[i][j] += a[i] * b[j];
        }
        int pk[4];
        #pragma unroll
        for (int j = 0; j < 4; j++) pk[j] = positions[k0 + tx*4 + j];
        #pragma unroll
        for (int i = 0; i < 4; i++)
            #pragma unroll
            for (int j = 0; j < 4; j++)
                s[i][j] = (pq[i] >= pk[j]) ? s[i][j] * 0.125f : -INFINITY;

        #pragma unroll
        for (int i = 0; i < 4; i++) {
            float mloc = s[i][0];
            #pragma unroll
            for (int j = 1; j < 4; j++) mloc = fmaxf(mloc, s[i][j]);
            #pragma unroll
            for (int o = 8; o; o >>= 1) mloc = fmaxf(mloc, __shfl_xor_sync(0xffffffffu, mloc, o));
            float mnew = fmaxf(m[i], mloc);
            float alpha = expf(m[i] - mnew);
            float ps = 0.f;
            #pragma unroll
            for (int j = 0; j < 4; j++) { float p = expf(s[i][j] - mnew); s[i][j] = p; ps += p; }
            #pragma unroll
            for (int o = 8; o; o >>= 1) ps += __shfl_xor_sync(0xffffffffu, ps, o);
            l[i] = l[i] * alpha + ps;
            m[i] = mnew;
            #pragma unroll
            for (int j = 0; j < 4; j++) O[i][j] *= alpha;
            #pragma unroll
            for (int j = 0; j < 4; j++) Ps[(ty*4 + i)*65 + tx*4 + j] = s[i][j];
        }
        __syncwarp();

        #pragma unroll 8
        for (int kk = 0; kk < 64; kk++) {
            float a[4], b[4];
            #pragma unroll
            for (int i = 0; i < 4; i++) a[i] = Ps[(ty*4 + i)*65 + kk];
            #pragma unroll
            for (int j = 0; j < 4; j++) b[j] = Vs[kk*65 + tx*4 + j];
            #pragma unroll
            for (int i = 0; i < 4; i++)
                #pragma unroll
                for (int j = 0; j < 4; j++) O[i][j] += a[i] * b[j];
        }
        __syncthreads();
    }
    #pragma unroll
    for (int i = 0; i < 4; i++)
        #pragma unroll
        for (int j = 0; j < 4; j++)
            g_attno[(size_t)(q0 + ty*4 + i)*H + h*HD + tx*4 + j] = O[i][j] / l[i];
}

// ---------------- router ------------------------------------------------------
__global__ void router_kernel(const float* __restrict__ Wg, const float* __restrict__ bias) {
    int t = blockIdx.x, tx = threadIdx.x;
    __shared__ float xs[H];
    __shared__ float scr[E], sfc[E];
    for (int hh = tx; hh < H; hh += 32) xs[hh] = g_x2[(size_t)t*H + hh];
    __syncthreads();
    float acc = 0.f;
    for (int hh = 0; hh < H; hh++) acc += xs[hh] * Wg[hh*E + tx];
    float sc = 1.f / (1.f + expf(-acc));
    scr[tx] = sc; sfc[tx] = sc + bias[tx];
    __syncthreads();
    if (tx == 0) {
        float gs[4];
        for (int g = 0; g < 4; g++) {
            float m1 = -INFINITY, m2 = -INFINITY;
            for (int j = 0; j < 8; j++) {
                float v = sfc[g*8 + j];
                if (v > m1) { m2 = m1; m1 = v; } else if (v > m2) m2 = v;
            }
            gs[g] = m1 + m2;
        }
        int g1 = 0;
        for (int g = 1; g < 4; g++) if (gs[g] > gs[g1]) g1 = g;
        int g2 = -1;
        for (int g = 0; g < 4; g++) { if (g == g1) continue; if (g2 < 0 || gs[g] > gs[g2]) g2 = g; }
        bool used[E];
        for (int e = 0; e < E; e++) used[e] = false;
        float wk[TOPK]; int idk[TOPK]; float wsum = 0.f;
        for (int k = 0; k < TOPK; k++) {
            int best = -1; float bv = -INFINITY;
            for (int e = 0; e < E; e++) {
                int g = e >> 3;
                if (g != g1 && g != g2) continue;
                if (used[e]) continue;
                if (sfc[e] > bv) { bv = sfc[e]; best = e; }
            }
            used[best] = true; idk[k] = best;
            wk[k] = scr[best]; wsum += wk[k];
        }
        for (int k = 0; k < TOPK; k++) {
            g_ids[t*TOPK + k] = idk[k];
            g_w[t*TOPK + k] = wk[k] / wsum;
            atomicAdd(&g_cnt[idk[k]], 1);
        }
    }
}

__global__ void zero_kernel() {
    int i = threadIdx.x;
    if (i < E) { g_cnt[i] = 0; g_fill[i] = 0; }
}

__global__ void scan_kernel() {
    if (threadIdx.x == 0) {
        int s = 0;
        for (int e = 0; e < E; e++) { g_off[e] = s; s += g_cnt[e]; }
    }
}

__global__ void scatter_kernel() {
    int t = blockIdx.x * blockDim.x + threadIdx.x;
    if (t >= T) return;
    for (int k = 0; k < TOPK; k++) {
        int e = g_ids[t*TOPK + k];
        int slot = g_off[e] + atomicAdd(&g_fill[e], 1);
        g_slot2tok[slot] = t;
        g_tokslot[t*TOPK + k] = slot;
    }
}

// ---------------- final combine ----------------------------------------------
__global__ void combine_kernel(float* __restrict__ out) {
    int t = blockIdx.x, tid = threadIdx.x;
    int s0 = g_tokslot[t*TOPK + 0], s1 = g_tokslot[t*TOPK + 1];
    int s2 = g_tokslot[t*TOPK + 2], s3 = g_tokslot[t*TOPK + 3];
    float w0 = g_w[t*TOPK + 0], w1 = g_w[t*TOPK + 1];
    float w2 = g_w[t*TOPK + 2], w3 = g_w[t*TOPK + 3];
    const float4* sh4 = (const float4*)(g_shared + (size_t)t*H);
    const float4* y0 = (const float4*)(g_y + (size_t)s0*H);
    const float4* y1 = (const float4*)(g_y + (size_t)s1*H);
    const float4* y2 = (const float4*)(g_y + (size_t)s2*H);
    const float4* y3 = (const float4*)(g_y + (size_t)s3*H);
    float4* o4 = (float4*)(out + (size_t)t*H);
    int c = tid;
    float4 a = sh4[c], v0 = y0[c], v1 = y1[c], v2 = y2[c], v3 = y3[c];
    o4[c] = make_float4(
        a.x + w0*v0.x + w1*v1.x + w2*v2.x + w3*v3.x,
        a.y + w0*v0.y + w1*v1.y + w2*v2.y + w3*v3.y,
        a.z + w0*v0.z + w1*v1.z + w2*v2.z + w3*v3.z,
        a.w + w0*v0.w + w1*v1.w + w2*v2.w + w3*v3.w);
}

// ---------------- host orchestration -----------------------------------------
extern "C" void kernel_launch(void* const* d_in, const int* in_sizes, int n_in,
                              void* d_out, int out_size) {
    const float* hidden   = (const float*)d_in[0];
    const float* residual = (const float*)d_in[1];
    const float* in_ln_w  = (const float*)d_in[2];
    const float* post_ln_w= (const float*)d_in[3];
    const float* q_norm_w = (const float*)d_in[4];
    const float* k_norm_w = (const float*)d_in[5];
    const float* Wqkv     = (const float*)d_in[6];
    const float* Wo       = (const float*)d_in[7];
    const float* Wg       = (const float*)d_in[8];
    const float* gate_bias= (const float*)d_in[9];
    const float* Wgu      = (const float*)d_in[10];
    const float* Wd       = (const float*)d_in[11];
    const float* Wgu_sh   = (const float*)d_in[12];
    const float* Wd_sh    = (const float*)d_in[13];
    const int*   positions= (const int*)d_in[14];
    float* out = (float*)d_out;

    float *p_res1, *p_qkv, *p_attno, *p_h, *p_x2, *p_gu, *p_y, *p_gus, *p_shared;
    bf16 *p_xhi, *p_xlo, *p_x2hi, *p_x2lo, *p_aohi, *p_aolo;
    bf16 *p_acthi, *p_actlo, *p_actshi, *p_actslo;
    bf16 *p_wqkvhi, *p_wqkvlo, *p_wohi, *p_wolo, *p_wguhi, *p_wgulo;
    bf16 *p_wdhi, *p_wdlo, *p_wgushi, *p_wguslo, *p_wdshi, *p_wdslo;

    cudaGetSymbolAddress((void**)&p_res1,  g_res1);
    cudaGetSymbolAddress((void**)&p_qkv,   g_qkv);
    cudaGetSymbolAddress((void**)&p_attno, g_attno);
    cudaGetSymbolAddress((void**)&p_h,     g_h);
    cudaGetSymbolAddress((void**)&p_x2,    g_x2);
    cudaGetSymbolAddress((void**)&p_gu,    g_gu);
    cudaGetSymbolAddress((void**)&p_y,     g_y);
    cudaGetSymbolAddress((void**)&p_gus,   g_gus);
    cudaGetSymbolAddress((void**)&p_shared,g_shared);
    cudaGetSymbolAddress((void**)&p_xhi,   g_xhi);
    cudaGetSymbolAddress((void**)&p_xlo,   g_xlo);
    cudaGetSymbolAddress((void**)&p_x2hi,  g_x2hi);
    cudaGetSymbolAddress((void**)&p_x2lo,  g_x2lo);
    cudaGetSymbolAddress((void**)&p_aohi,  g_aohi);
    cudaGetSymbolAddress((void**)&p_aolo,  g_aolo);
    cudaGetSymbolAddress((void**)&p_acthi, g_acthi);
    cudaGetSymbolAddress((void**)&p_actlo, g_actlo);
    cudaGetSymbolAddress((void**)&p_actshi,g_actshi);
    cudaGetSymbolAddress((void**)&p_actslo,g_actslo);
    cudaGetSymbolAddress((void**)&p_wqkvhi,g_wqkvhi);
    cudaGetSymbolAddress((void**)&p_wqkvlo,g_wqkvlo);
    cudaGetSymbolAddress((void**)&p_wohi,  g_wohi);
    cudaGetSymbolAddress((void**)&p_wolo,  g_wolo);
    cudaGetSymbolAddress((void**)&p_wguhi, g_wguhi);
    cudaGetSymbolAddress((void**)&p_wgulo, g_wgulo);
    cudaGetSymbolAddress((void**)&p_wdhi,  g_wdhi);
    cudaGetSymbolAddress((void**)&p_wdlo,  g_wdlo);
    cudaGetSymbolAddress((void**)&p_wgushi,g_wgushi);
    cudaGetSymbolAddress((void**)&p_wguslo,g_wguslo);
    cudaGetSymbolAddress((void**)&p_wdshi, g_wdshi);
    cudaGetSymbolAddress((void**)&p_wdslo, g_wdslo);

    cudaFuncSetAttribute(tc_gemm, cudaFuncAttributeMaxDynamicSharedMemorySize, GSM_TOTAL);
    cudaFuncSetAttribute(attn_kernel, cudaFuncAttributeMaxDynamicSharedMemorySize, 4*64*65*4);

    dim3 wblk(32, 8);

    // 1. residual1 = hidden + residual ; x = rms(...) -> bf16 split only
    add_rmsnorm_kernel<<<T, 256>>>(hidden, residual, p_res1, in_ln_w, nullptr, p_xhi, p_xlo);

    // 2. qkv = x @ Wqkv
    wsplitT<<<dim3(QKVW/32, H/32, 1), wblk>>>(Wqkv, p_wqkvhi, p_wqkvlo, H, QKVW);
    tc_gemm<<<dim3(QKVW/128, T/128), 256, GSM_TOTAL>>>(p_xhi, p_xlo, p_wqkvhi, p_wqkvlo,
                                                       p_qkv, QKVW, H, 0, 0);

    // 3. q/k rmsnorm + rope
    qknorm_rope_kernel<<<dim3(T, NH + NKV), 32>>>(q_norm_w, k_norm_w, positions);

    // 4. attention
    attn_kernel<<<dim3(T/64, NH), 256, 4*64*65*4>>>(positions);

    // 5. h = attno @ Wo ; residual2 -> out ; x2 = rms(residual2)
    split_kernel<<<(T*H/4 + 255)/256, 256>>>(p_attno, p_aohi, p_aolo, T*H);
    wsplitT<<<dim3(H/32, H/32, 1), wblk>>>(Wo, p_wohi, p_wolo, H, H);
    tc_gemm<<<dim3(H/128, T/128), 256, GSM_TOTAL>>>(p_aohi, p_aolo, p_wohi, p_wolo,
                                                    p_h, H, H, 0, 0);
    float* out_res = out + (size_t)T*H;
    add_rmsnorm_kernel<<<T, 256>>>(p_h, p_res1, out_res, post_ln_w, p_x2, p_x2hi, p_x2lo);

    // 6. router + dispatch
    zero_kernel<<<1, 32>>>();
    router_kernel<<<T, 32>>>(Wg, gate_bias);
    scan_kernel<<<1, 1>>>();
    scatter_kernel<<<(T + 255)/256, 256>>>();

    // 7. routed experts
    wsplitT<<<dim3(2*IM/32, H/32, E), wblk>>>(Wgu, p_wguhi, p_wgulo, H, 2*IM);
    tc_gemm<<<dim3(2*IM/128, NSLOT/128, E), 256, GSM_TOTAL>>>(p_x2hi, p_x2lo, p_wguhi, p_wgulo,
                                                              p_gu, 2*IM, H, 1, 1);
    silu_split<<<(NSLOT*IM + 255)/256, 256>>>(p_gu, p_acthi, p_actlo, NSLOT*IM);
    wsplitT<<<dim3(H/32, IM/32, E), wblk>>>(Wd, p_wdhi, p_wdlo, IM, H);
    tc_gemm<<<dim3(H/128, NSLOT/128, E), 256, GSM_TOTAL>>>(p_acthi, p_actlo, p_wdhi, p_wdlo,
                                                           p_y, H, IM, 1, 0);

    // 8. shared expert
    wsplitT<<<dim3(2*IM/32, H/32, 1), wblk>>>(Wgu_sh, p_wgushi, p_wguslo, H, 2*IM);
    tc_gemm<<<dim3(2*IM/128, T/128), 256, GSM_TOTAL>>>(p_x2hi, p_x2lo, p_wgushi, p_wguslo,
                                                       p_gus, 2*IM, H, 0, 0);
    silu_split<<<(T*IM + 255)/256, 256>>>(p_gus, p_actshi, p_actslo, T*IM);
    wsplitT<<<dim3(H/32, IM/32, 1), wblk>>>(Wd_sh, p_wdshi, p_wdslo, IM, H);
    tc_gemm<<<dim3(H/128, T/128), 256, GSM_TOTAL>>>(p_actshi, p_actslo, p_wdshi, p_wdslo,
                                                    p_shared, H, IM, 0, 0);

    // 9. combine
    combine_kernel<<<T, 256>>>(out);
}

// round 14
// speedup vs baseline: 1.5315x; 1.2222x over previous
#include <cuda_runtime.h>
#include <cuda_bf16.h>
#include <math.h>
#include <stdint.h>

#define T 2048
#define H 1024
#define NH 16
#define NKV 4
#define HD 64
#define E 32
#define TOPK 4
#define IM 384
#define QKVW 1536   // (NH + 2*NKV) * HD
#define NSLOT (T*TOPK)

typedef __nv_bfloat16 bf16;

// ---------------- scratch (device globals; no allocation allowed) ------------
__device__ float g_res1[T*H];
__device__ float g_qkv[T*QKVW];
__device__ float g_attno[T*H];
__device__ float g_h[T*H];
__device__ float g_x2[T*H];
__device__ float g_gu[NSLOT*2*IM];
__device__ float g_y[(size_t)NSLOT*H];
__device__ float g_gus[T*2*IM];
__device__ float g_shared[T*H];
__device__ int   g_ids[T*TOPK];
__device__ float g_w[T*TOPK];
__device__ int   g_cnt[E];
__device__ int   g_off[E];
__device__ int   g_fill[E];
__device__ int   g_slot2tok[NSLOT];
__device__ int   g_tokslot[T*TOPK];

// bf16 split activations
__device__ bf16 g_xhi[T*H],   g_xlo[T*H];
__device__ bf16 g_x2hi[T*H],  g_x2lo[T*H];
__device__ bf16 g_aohi[T*H],  g_aolo[T*H];
__device__ bf16 g_acthi[NSLOT*IM],  g_actlo[NSLOT*IM];
__device__ bf16 g_actshi[T*IM],     g_actslo[T*IM];
__device__ bf16 g_qkvhi[(size_t)T*QKVW], g_qkvlo[(size_t)T*QKVW];
// bf16 split + transposed weights ([N,K] layout, per-expert contiguous)
__device__ bf16 g_wqkvhi[(size_t)QKVW*H], g_wqkvlo[(size_t)QKVW*H];
__device__ bf16 g_wohi[(size_t)H*H],      g_wolo[(size_t)H*H];
__device__ bf16 g_wguhi[(size_t)E*2*IM*H], g_wgulo[(size_t)E*2*IM*H];
__device__ bf16 g_wdhi[(size_t)E*H*IM],    g_wdlo[(size_t)E*H*IM];
__device__ bf16 g_wgushi[(size_t)2*IM*H],  g_wguslo[(size_t)2*IM*H];
__device__ bf16 g_wdshi[(size_t)H*IM],     g_wdslo[(size_t)H*IM];

__device__ __forceinline__ uint32_t smem_u32(const void* p) {
    uint32_t a;
    asm("{ .reg .u64 t; cvta.to.shared.u64 t, %1; cvt.u32.u64 %0, t; }" : "=r"(a) : "l"(p));
    return a;
}

#define CP8(s, g, sz) \
    asm volatile("cp.async.ca.shared.global [%0], [%1], 8, %2;" :: "r"(s), "l"(g), "r"(sz))
#define CP16(s, g) \
    asm volatile("cp.async.cg.shared.global [%0], [%1], 16;" :: "r"(s), "l"(g))
#define CP_COMMIT() asm volatile("cp.async.commit_group;" ::: "memory")
#define CP_WAIT1()  asm volatile("cp.async.wait_group 1;" ::: "memory")
#define CP_WAIT0()  asm volatile("cp.async.wait_group 0;" ::: "memory")

#define MMA_BF16(c, a, b) \
    asm volatile("mma.sync.aligned.m16n8k16.row.col.f32.bf16.bf16.f32 " \
        "{%0,%1,%2,%3}, {%4,%5,%6,%7}, {%8,%9}, {%0,%1,%2,%3};" \
        : "+f"((c)[0]), "+f"((c)[1]), "+f"((c)[2]), "+f"((c)[3]) \
        : "r"((a)[0]), "r"((a)[1]), "r"((a)[2]), "r"((a)[3]), "r"((b)[0]), "r"((b)[1]))

__device__ __forceinline__ uint32_t packbf2(float a, float b) {
    __nv_bfloat162 t = __floats2bfloat162_rn(a, b);
    return *(uint32_t*)&t;
}

// ======================= tensor-core GEMM (mma.sync) =========================
#define GP 40
#define TILE_B (128*GP*2)
#define OFF_ALO (1*TILE_B)
#define OFF_BHI (2*TILE_B)
#define OFF_BLO (3*TILE_B)
#define CHUNK_B (4*TILE_B)
#define GSM_TOTAL (2*CHUNK_B)

__global__ __launch_bounds__(256) void tc_gemm(
    const bf16* __restrict__ Ahi, const bf16* __restrict__ Alo,
    const bf16* __restrict__ Bhi, const bf16* __restrict__ Blo,
    float* __restrict__ C, int N, int K, int moe, int gather)
{
    extern __shared__ __align__(16) char dsm[];
    int tid = threadIdx.x;
    int warp = tid >> 5, lane = tid & 31;
    int wm = warp & 1, wn = warp >> 1;
    int g = lane >> 2, t2 = (lane & 3) * 2;
    int bn = blockIdx.x * 128;
    int bm = blockIdx.y * 128;

    int cnt = 0, basem = 0;
    const bf16* bh = Bhi; const bf16* bl = Blo;
    if (moe) {
        int e = blockIdx.z;
        cnt = g_cnt[e];
        if (bm >= cnt) return;
        basem = g_off[e];
        size_t ws = (size_t)N * K;
        bh += ws * (size_t)e; bl += ws * (size_t)e;
    }

    int r = tid >> 1, h = tid & 1;
    long arow;
    uint32_t asz = 8;
    if (moe) {
        int rr = bm + r;
        if (rr < cnt) arow = gather ? (long)g_slot2tok[basem + rr] : (long)(basem + rr);
        else { arow = 0; asz = 0; }
    } else arow = bm + r;
    long brow = bn + r;

    uint32_t sbase = smem_u32(dsm);
    uint32_t srow = (uint32_t)(r * GP + h * 16) * 2;

    auto prefetch = [&](int c, int b) {
        size_t ka = (size_t)c * 32 + h * 16;
        uint32_t sb = sbase + b * CHUNK_B + srow;
        const bf16* gah = Ahi + arow * K + ka;
        const bf16* gal = Alo + arow * K + ka;
        const bf16* gbh = bh + brow * K + ka;
        const bf16* gbl = bl + brow * K + ka;
        #pragma unroll
        for (int i = 0; i < 4; i++) {
            CP8(sb + i*8,           gah + i*4, asz);
            CP8(sb + OFF_ALO + i*8, gal + i*4, asz);
            CP8(sb + OFF_BHI + i*8, gbh + i*4, 8u);
            CP8(sb + OFF_BLO + i*8, gbl + i*4, 8u);
        }
    };

    float acc[4][4][4];
    #pragma unroll
    for (int mi = 0; mi < 4; mi++)
        #pragma unroll
        for (int ni = 0; ni < 4; ni++)
            #pragma unroll
            for (int q = 0; q < 4; q++) acc[mi][ni][q] = 0.f;

    int NC = K / 32;
    prefetch(0, 0);
    CP_COMMIT();

    for (int c = 0; c < NC; c++) {
        int b = c & 1;
        if (c + 1 < NC) prefetch(c + 1, b ^ 1);
        CP_COMMIT();
        CP_WAIT1();
        __syncthreads();

        const bf16* Ah = (const bf16*)(dsm + b * CHUNK_B);
        const bf16* Al = (const bf16*)(dsm + b * CHUNK_B + OFF_ALO);
        const bf16* Bh = (const bf16*)(dsm + b * CHUNK_B + OFF_BHI);
        const bf16* Bl = (const bf16*)(dsm + b * CHUNK_B + OFF_BLO);

        #pragma unroll
        for (int ks = 0; ks < 2; ks++) {
            int ko = ks * 16;
            uint32_t ah[4][4], al[4][4], bhf[4][2], blf[4][2];
            #pragma unroll
            for (int mi = 0; mi < 4; mi++) {
                int row = wm * 64 + mi * 16 + g;
                ah[mi][0] = *(const uint32_t*)&Ah[row * GP + ko + t2];
                ah[mi][1] = *(const uint32_t*)&Ah[(row + 8) * GP + ko + t2];
                ah[mi][2] = *(const uint32_t*)&Ah[row * GP + ko + t2 + 8];
                ah[mi][3] = *(const uint32_t*)&Ah[(row + 8) * GP + ko + t2 + 8];
                al[mi][0] = *(const uint32_t*)&Al[row * GP + ko + t2];
                al[mi][1] = *(const uint32_t*)&Al[(row + 8) * GP + ko + t2];
                al[mi][2] = *(const uint32_t*)&Al[row * GP + ko + t2 + 8];
                al[mi][3] = *(const uint32_t*)&Al[(row + 8) * GP + ko + t2 + 8];
            }
            #pragma unroll
            for (int ni = 0; ni < 4; ni++) {
                int nr = wn * 32 + ni * 8 + g;
                bhf[ni][0] = *(const uint32_t*)&Bh[nr * GP + ko + t2];
                bhf[ni][1] = *(const uint32_t*)&Bh[nr * GP + ko + t2 + 8];
                blf[ni][0] = *(const uint32_t*)&Bl[nr * GP + ko + t2];
                blf[ni][1] = *(const uint32_t*)&Bl[nr * GP + ko + t2 + 8];
            }
            #pragma unroll
            for (int mi = 0; mi < 4; mi++)
                #pragma unroll
                for (int ni = 0; ni < 4; ni++) {
                    MMA_BF16(acc[mi][ni], ah[mi], bhf[ni]);
                    MMA_BF16(acc[mi][ni], ah[mi], blf[ni]);
                    MMA_BF16(acc[mi][ni], al[mi], bhf[ni]);
                }
        }
        __syncthreads();
    }

    #pragma unroll
    for (int mi = 0; mi < 4; mi++) {
        int lr0 = bm + wm * 64 + mi * 16 + g;
        int lr1 = lr0 + 8;
        bool v0 = moe ? (lr0 < cnt) : true;
        bool v1 = moe ? (lr1 < cnt) : true;
        size_t ro0 = ((size_t)(moe ? basem : 0) + lr0) * N;
        size_t ro1 = ((size_t)(moe ? basem : 0) + lr1) * N;
        #pragma unroll
        for (int ni = 0; ni < 4; ni++) {
            int col = bn + wn * 32 + ni * 8 + t2;
            if (v0) *(float2*)&C[ro0 + col] = make_float2(acc[mi][ni][0], acc[mi][ni][1]);
            if (v1) *(float2*)&C[ro1 + col] = make_float2(acc[mi][ni][2], acc[mi][ni][3]);
        }
    }
}

// ================= tensor-core flash attention ===============================
// One CTA per (q-tile of 128, head). 8 warps x 16 q-rows. K/V tiles of 64.
// S = QK^T and O = PV via mma.sync bf16 with 3-term hi/lo split.
#define AP 72
#define ASM_TOTAL ((128*2 + 64*4)*AP*2)   // bytes

__global__ __launch_bounds__(256) void tc_attn() {
    extern __shared__ __align__(16) bf16 smA[];
    bf16* Qhi = smA;
    bf16* Qlo = Qhi + 128*AP;
    bf16* Khi = Qlo + 128*AP;
    bf16* Klo = Khi + 64*AP;
    bf16* Vhi = Klo + 64*AP;   // transposed: [dim][key]
    bf16* Vlo = Vhi + 64*AP;

    int h = blockIdx.y;
    int qt = (int)gridDim.x - 1 - (int)blockIdx.x;   // big tiles first
    int q0 = qt * 128;
    int kvh = h >> 2;
    int tid = threadIdx.x, warp = tid >> 5, lane = tid & 31;
    int g = lane >> 2, t2 = (lane & 3) * 2;

    // ---- load Q tile (hi/lo), 128 rows x 64 dims
    {
        int r = tid >> 1, hf = tid & 1;
        const bf16* sh = g_qkvhi + (size_t)(q0 + r)*QKVW + h*HD + hf*32;
        const bf16* sl = g_qkvlo + (size_t)(q0 + r)*QKVW + h*HD + hf*32;
        uint32_t dh = smem_u32(Qhi + r*AP + hf*32);
        uint32_t dl = smem_u32(Qlo + r*AP + hf*32);
        #pragma unroll
        for (int i = 0; i < 4; i++) { CP16(dh + i*16, sh + i*8); CP16(dl + i*16, sl + i*8); }
    }
    CP_COMMIT(); CP_WAIT0(); __syncthreads();

    // preload Q fragments (registers, reused across all k-tiles)
    uint32_t qh[4][4], ql[4][4];
    {
        int qrow = warp*16 + g;
        #pragma unroll
        for (int ks = 0; ks < 4; ks++) {
            int ko = ks * 16;
            qh[ks][0] = *(const uint32_t*)&Qhi[qrow*AP + ko + t2];
            qh[ks][1] = *(const uint32_t*)&Qhi[(qrow+8)*AP + ko + t2];
            qh[ks][2] = *(const uint32_t*)&Qhi[qrow*AP + ko + t2 + 8];
            qh[ks][3] = *(const uint32_t*)&Qhi[(qrow+8)*AP + ko + t2 + 8];
            ql[ks][0] = *(const uint32_t*)&Qlo[qrow*AP + ko + t2];
            ql[ks][1] = *(const uint32_t*)&Qlo[(qrow+8)*AP + ko + t2];
            ql[ks][2] = *(const uint32_t*)&Qlo[qrow*AP + ko + t2 + 8];
            ql[ks][3] = *(const uint32_t*)&Qlo[(qrow+8)*AP + ko + t2 + 8];
        }
    }

    float accO[8][4];
    #pragma unroll
    for (int od = 0; od < 8; od++)
        #pragma unroll
        for (int q = 0; q < 4; q++) accO[od][q] = 0.f;
    float m0 = -INFINITY, m1 = -INFINITY, l0 = 0.f, l1 = 0.f;
    int r0 = q0 + warp*16 + g, r1 = r0 + 8;

    int ntiles = 2*qt + 2;
    for (int jt = 0; jt < ntiles; jt++) {
        int k0 = jt * 64;
        // load K tile (hi/lo) [key][dim]
        {
            int r = tid >> 2, q4 = tid & 3;
            const bf16* sh = g_qkvhi + (size_t)(k0 + r)*QKVW + NH*HD + kvh*HD + q4*16;
            const bf16* sl = g_qkvlo + (size_t)(k0 + r)*QKVW + NH*HD + kvh*HD + q4*16;
            uint32_t dh = smem_u32(Khi + r*AP + q4*16);
            uint32_t dl = smem_u32(Klo + r*AP + q4*16);
            CP16(dh, sh); CP16(dh + 16, sh + 8);
            CP16(dl, sl); CP16(dl + 16, sl + 8);
        }
        // load V tile transposed -> [dim][key]
        {
            int vr = tid >> 2, vq = (tid & 3) * 8;
            const uint32_t* ph = (const uint32_t*)(g_qkvhi + (size_t)(k0 + vr)*QKVW + (NH+NKV)*HD + kvh*HD) + vq;
            const uint32_t* pl = (const uint32_t*)(g_qkvlo + (size_t)(k0 + vr)*QKVW + (NH+NKV)*HD + kvh*HD) + vq;
            #pragma unroll
            for (int j = 0; j < 8; j++) {
                uint32_t wh = ph[j], wl = pl[j];
                int d0 = 2*(vq + j);
                __nv_bfloat162 vh = *(__nv_bfloat162*)&wh;
                __nv_bfloat162 vl = *(__nv_bfloat162*)&wl;
                Vhi[d0*AP + vr] = vh.x; Vhi[(d0+1)*AP + vr] = vh.y;
                Vlo[d0*AP + vr] = vl.x; Vlo[(d0+1)*AP + vr] = vl.y;
            }
        }
        CP_COMMIT(); CP_WAIT0(); __syncthreads();

        // ---- S = Q @ K^T (3-term split)
        float s[8][4];
        #pragma unroll
        for (int nb = 0; nb < 8; nb++)
            #pragma unroll
            for (int q = 0; q < 4; q++) s[nb][q] = 0.f;
        #pragma unroll
        for (int ks = 0; ks < 4; ks++) {
            int ko = ks * 16;
            #pragma unroll
            for (int nb = 0; nb < 8; nb++) {
                int nr = nb*8 + g;
                uint32_t bh[2], bl[2];
                bh[0] = *(const uint32_t*)&Khi[nr*AP + ko + t2];
                bh[1] = *(const uint32_t*)&Khi[nr*AP + ko + t2 + 8];
                bl[0] = *(const uint32_t*)&Klo[nr*AP + ko + t2];
                bl[1] = *(const uint32_t*)&Klo[nr*AP + ko + t2 + 8];
                MMA_BF16(s[nb], qh[ks], bh);
                MMA_BF16(s[nb], qh[ks], bl);
                MMA_BF16(s[nb], ql[ks], bh);
            }
        }
        // scale + causal mask
        #pragma unroll
        for (int nb = 0; nb < 8; nb++)
            #pragma unroll
            for (int q = 0; q < 4; q++) s[nb][q] *= 0.125f;
        if (jt >= 2*qt) {
            #pragma unroll
            for (int nb = 0; nb < 8; nb++) {
                int c0 = k0 + nb*8 + t2, c1 = c0 + 1;
                if (c0 > r0) s[nb][0] = -INFINITY;
                if (c1 > r0) s[nb][1] = -INFINITY;
                if (c0 > r1) s[nb][2] = -INFINITY;
                if (c1 > r1) s[nb][3] = -INFINITY;
            }
        }
        // ---- online softmax
        float mx0 = -INFINITY, mx1 = -INFINITY;
        #pragma unroll
        for (int nb = 0; nb < 8; nb++) {
            mx0 = fmaxf(mx0, fmaxf(s[nb][0], s[nb][1]));
            mx1 = fmaxf(mx1, fmaxf(s[nb][2], s[nb][3]));
        }
        mx0 = fmaxf(mx0, __shfl_xor_sync(0xffffffffu, mx0, 1));
        mx0 = fmaxf(mx0, __shfl_xor_sync(0xffffffffu, mx0, 2));
        mx1 = fmaxf(mx1, __shfl_xor_sync(0xffffffffu, mx1, 1));
        mx1 = fmaxf(mx1, __shfl_xor_sync(0xffffffffu, mx1, 2));
        float mn0 = fmaxf(m0, mx0), mn1 = fmaxf(m1, mx1);
        float al0 = __expf(m0 - mn0), al1 = __expf(m1 - mn1);
        m0 = mn0; m1 = mn1;
        float ps0 = 0.f, ps1 = 0.f;
        #pragma unroll
        for (int nb = 0; nb < 8; nb++) {
            s[nb][0] = __expf(s[nb][0] - mn0); ps0 += s[nb][0];
            s[nb][1] = __expf(s[nb][1] - mn0); ps0 += s[nb][1];
            s[nb][2] = __expf(s[nb][2] - mn1); ps1 += s[nb][2];
            s[nb][3] = __expf(s[nb][3] - mn1); ps1 += s[nb][3];
        }
        l0 = l0*al0 + ps0; l1 = l1*al1 + ps1;
        #pragma unroll
        for (int od = 0; od < 8; od++) {
            accO[od][0] *= al0; accO[od][1] *= al0;
            accO[od][2] *= al1; accO[od][3] *= al1;
        }
        // ---- O += P @ V (3-term split, P repacked from S accumulators)
        #pragma unroll
        for (int ks = 0; ks < 4; ks++) {
            uint32_t aph[4], apl[4];
            #pragma unroll
            for (int half = 0; half < 2; half++) {
                int nb = 2*ks + half;
                float p0 = s[nb][0], p1 = s[nb][1], p2 = s[nb][2], p3 = s[nb][3];
                bf16 h0 = __float2bfloat16(p0), h1 = __float2bfloat16(p1);
                bf16 h2 = __float2bfloat16(p2), h3 = __float2bfloat16(p3);
                __nv_bfloat162 t01; t01.x = h0; t01.y = h1;
                aph[half*2 + 0] = *(uint32_t*)&t01;
                __nv_bfloat162 t23; t23.x = h2; t23.y = h3;
                aph[half*2 + 1] = *(uint32_t*)&t23;
                apl[half*2 + 0] = packbf2(p0 - __bfloat162float(h0), p1 - __bfloat162float(h1));
                apl[half*2 + 1] = packbf2(p2 - __bfloat162float(h2), p3 - __bfloat162float(h3));
            }
            int ko = ks * 16;
            #pragma unroll
            for (int od = 0; od < 8; od++) {
                int nr = od*8 + g;
                uint32_t bh[2], bl[2];
                bh[0] = *(const uint32_t*)&Vhi[nr*AP + ko + t2];
                bh[1] = *(const uint32_t*)&Vhi[nr*AP + ko + t2 + 8];
                bl[0] = *(const uint32_t*)&Vlo[nr*AP + ko + t2];
                bl[1] = *(const uint32_t*)&Vlo[nr*AP + ko + t2 + 8];
                MMA_BF16(accO[od], aph, bh);
                MMA_BF16(accO[od], aph, bl);
                MMA_BF16(accO[od], apl, bh);
            }
        }
        __syncthreads();   // K/V smem reused next tile
    }

    // final: reduce l across quad, divide, store
    l0 += __shfl_xor_sync(0xffffffffu, l0, 1);
    l0 += __shfl_xor_sync(0xffffffffu, l0, 2);
    l1 += __shfl_xor_sync(0xffffffffu, l1, 1);
    l1 += __shfl_xor_sync(0xffffffffu, l1, 2);
    float inv0 = 1.f / l0, inv1 = 1.f / l1;
    #pragma unroll
    for (int od = 0; od < 8; od++) {
        int col = h*HD + od*8 + t2;
        *(float2*)&g_attno[(size_t)r0*H + col] = make_float2(accO[od][0]*inv0, accO[od][1]*inv0);
        *(float2*)&g_attno[(size_t)r1*H + col] = make_float2(accO[od][2]*inv1, accO[od][3]*inv1);
    }
}

// ===================== conversion kernels ====================================
__global__ void split_kernel(const float* __restrict__ x, bf16* __restrict__ hi,
                             bf16* __restrict__ lo, int n) {
    int i = (blockIdx.x * blockDim.x + threadIdx.x) * 4;
    if (i >= n) return;
    float4 v = *(const float4*)(x + i);
    bf16 h0 = __float2bfloat16(v.x), h1 = __float2bfloat16(v.y);
    bf16 h2 = __float2bfloat16(v.z), h3 = __float2bfloat16(v.w);
    bf16 l0 = __float2bfloat16(v.x - __bfloat162float(h0));
    bf16 l1 = __float2bfloat16(v.y - __bfloat162float(h1));
    bf16 l2 = __float2bfloat16(v.z - __bfloat162float(h2));
    bf16 l3 = __float2bfloat16(v.w - __bfloat162float(h3));
    __nv_bfloat162* Hp = (__nv_bfloat162*)(hi + i);
    __nv_bfloat162* Lp = (__nv_bfloat162*)(lo + i);
    Hp[0] = __halves2bfloat162(h0, h1); Hp[1] = __halves2bfloat162(h2, h3);
    Lp[0] = __halves2bfloat162(l0, l1); Lp[1] = __halves2bfloat162(l2, l3);
}

__global__ void wsplitT(const float* __restrict__ W, bf16* __restrict__ hi,
                        bf16* __restrict__ lo, int K, int N) {
    size_t ws = (size_t)K * N * blockIdx.z;
    const float* Wp = W + ws;
    bf16* hp = hi + ws; bf16* lp = lo + ws;
    __shared__ float tl[32][33];
    int n0 = blockIdx.x * 32, k0 = blockIdx.y * 32;
    int tx = threadIdx.x, ty = threadIdx.y;
    #pragma unroll
    for (int j = 0; j < 4; j++) {
        int k = ty + j * 8;
        tl[k][tx] = Wp[(size_t)(k0 + k) * N + n0 + tx];
    }
    __syncthreads();
    #pragma unroll
    for (int j = 0; j < 4; j++) {
        int nl = ty + j * 8;
        float v = tl[tx][nl];
        bf16 h = __float2bfloat16(v);
        size_t o = (size_t)(n0 + nl) * K + k0 + tx;
        hp[o] = h;
        lp[o] = __float2bfloat16(v - __bfloat162float(h));
    }
}

__global__ void add_rmsnorm_kernel(const float* __restrict__ a, const float* __restrict__ b,
                                   float* __restrict__ res, const float* __restrict__ w,
                                   float* __restrict__ y, bf16* __restrict__ yhi,
                                   bf16* __restrict__ ylo) {
    int t = blockIdx.x, tid = threadIdx.x;
    __shared__ float red[256];
    const float4* a4 = (const float4*)(a + (size_t)t * H);
    const float4* b4 = (const float4*)(b + (size_t)t * H);
    float4 va = a4[tid], vb = b4[tid];
    float4 v = make_float4(va.x + vb.x, va.y + vb.y, va.z + vb.z, va.w + vb.w);
    ((float4*)(res + (size_t)t * H))[tid] = v;
    float s = v.x*v.x + v.y*v.y + v.z*v.z + v.w*v.w;
    red[tid] = s; __syncthreads();
    for (int o = 128; o; o >>= 1) { if (tid < o) red[tid] += red[tid + o]; __syncthreads(); }
    float inv = rsqrtf(red[0] / (float)H + 1e-5f);
    float4 wv = ((const float4*)w)[tid];
    float4 o4 = make_float4(v.x*inv*wv.x, v.y*inv*wv.y, v.z*inv*wv.z, v.w*inv*wv.w);
    if (y) ((float4*)(y + (size_t)t * H))[tid] = o4;
    bf16 h0 = __float2bfloat16(o4.x), h1 = __float2bfloat16(o4.y);
    bf16 h2 = __float2bfloat16(o4.z), h3 = __float2bfloat16(o4.w);
    bf16 l0 = __float2bfloat16(o4.x - __bfloat162float(h0));
    bf16 l1 = __float2bfloat16(o4.y - __bfloat162float(h1));
    bf16 l2 = __float2bfloat16(o4.z - __bfloat162float(h2));
    bf16 l3 = __float2bfloat16(o4.w - __bfloat162float(h3));
    __nv_bfloat162* Hp = (__nv_bfloat162*)(yhi + (size_t)t * H) + tid * 2;
    __nv_bfloat162* Lp = (__nv_bfloat162*)(ylo + (size_t)t * H) + tid * 2;
    Hp[0] = __halves2bfloat162(h0, h1); Hp[1] = __halves2bfloat162(h2, h3);
    Lp[0] = __halves2bfloat162(l0, l1); Lp[1] = __halves2bfloat162(l2, l3);
}

__global__ void silu_split(const float* __restrict__ gu, bf16* __restrict__ hi,
                           bf16* __restrict__ lo, int total) {
    int i = blockIdx.x * blockDim.x + threadIdx.x;
    if (i >= total) return;
    int r = i / IM, c = i % IM;
    float g = gu[(size_t)r*2*IM + c], u = gu[(size_t)r*2*IM + IM + c];
    float a = g * (1.f / (1.f + expf(-g))) * u;
    bf16 h = __float2bfloat16(a);
    hi[i] = h;
    lo[i] = __float2bfloat16(a - __bfloat162float(h));
}

// ---------------- Q/K rmsnorm + RoPE (warp per head, 8 warps/CTA) ------------
__global__ void qknorm_rope_kernel(const float* __restrict__ qw, const float* __restrict__ kw,
                                   const int* __restrict__ pos) {
    int idx = blockIdx.x * 8 + (threadIdx.x >> 5);
    if (idx >= T * (NH + NKV)) return;
    int t = idx / (NH + NKV), hh = idx % (NH + NKV);
    float* v;
    const float* w;
    if (hh < NH) { v = g_qkv + (size_t)t*QKVW + hh*HD; w = qw; }
    else         { v = g_qkv + (size_t)t*QKVW + NH*HD + (hh-NH)*HD; w = kw; }
    int lane = threadIdx.x & 31;
    int warp = threadIdx.x >> 5;
    float a = v[lane], b = v[lane + 32];
    float ss = a*a + b*b;
    #pragma unroll
    for (int o = 16; o; o >>= 1) ss += __shfl_xor_sync(0xffffffffu, ss, o);
    float inv = rsqrtf(ss / (float)HD + 1e-5f);
    a *= inv * w[lane]; b *= inv * w[lane + 32];
    __shared__ float sh[8][64];
    sh[warp][lane] = a; sh[warp][lane + 32] = b;
    __syncwarp();
    float p = (float)pos[t];
    if (lane < 16) {
        float invf = expf(-((float)lane / 16.f) * logf(10000.f));
        float ang = p * invf;
        float c = cosf(ang), s = sinf(ang);
        float x1 = sh[warp][lane], x2 = sh[warp][lane + 16];
        v[lane]      = x1*c - x2*s;
        v[lane + 16] = x1*s + x2*c;
    } else {
        v[lane + 16] = sh[warp][lane + 16];
        v[lane + 32] = sh[warp][lane + 32];
    }
}

// ---------------- router ------------------------------------------------------
__global__ void router_kernel(const float* __restrict__ Wg, const float* __restrict__ bias) {
    int t = blockIdx.x, tx = threadIdx.x;
    __shared__ float xs[H];
    __shared__ float scr[E], sfc[E];
    for (int hh = tx; hh < H; hh += 32) xs[hh] = g_x2[(size_t)t*H + hh];
    __syncthreads();
    float acc = 0.f;
    for (int hh = 0; hh < H; hh++) acc += xs[hh] * Wg[hh*E + tx];
    float sc = 1.f / (1.f + expf(-acc));
    scr[tx] = sc; sfc[tx] = sc + bias[tx];
    __syncthreads();
    if (tx == 0) {
        float gs[4];
        for (int g = 0; g < 4; g++) {
            float m1 = -INFINITY, m2 = -INFINITY;
            for (int j = 0; j < 8; j++) {
                float v = sfc[g*8 + j];
                if (v > m1) { m2 = m1; m1 = v; } else if (v > m2) m2 = v;
            }
            gs[g] = m1 + m2;
        }
        int g1 = 0;
        for (int g = 1; g < 4; g++) if (gs[g] > gs[g1]) g1 = g;
        int g2 = -1;
        for (int g = 0; g < 4; g++) { if (g == g1) continue; if (g2 < 0 || gs[g] > gs[g2]) g2 = g; }
        bool used[E];
        for (int e = 0; e < E; e++) used[e] = false;
        float wk[TOPK]; int idk[TOPK]; float wsum = 0.f;
        for (int k = 0; k < TOPK; k++) {
            int best = -1; float bv = -INFINITY;
            for (int e = 0; e < E; e++) {
                int g = e >> 3;
                if (g != g1 && g != g2) continue;
                if (used[e]) continue;
                if (sfc[e] > bv) { bv = sfc[e]; best = e; }
            }
            used[best] = true; idk[k] = best;
            wk[k] = scr[best]; wsum += wk[k];
        }
        for (int k = 0; k < TOPK; k++) {
            g_ids[t*TOPK + k] = idk[k];
            g_w[t*TOPK + k] = wk[k] / wsum;
            atomicAdd(&g_cnt[idk[k]], 1);
        }
    }
}

__global__ void zero_kernel() {
    int i = threadIdx.x;
    if (i < E) { g_cnt[i] = 0; g_fill[i] = 0; }
}

__global__ void scan_kernel() {
    if (threadIdx.x == 0) {
        int s = 0;
        for (int e = 0; e < E; e++) { g_off[e] = s; s += g_cnt[e]; }
    }
}

__global__ void scatter_kernel() {
    int t = blockIdx.x * blockDim.x + threadIdx.x;
    if (t >= T) return;
    for (int k = 0; k < TOPK; k++) {
        int e = g_ids[t*TOPK + k];
        int slot = g_off[e] + atomicAdd(&g_fill[e], 1);
        g_slot2tok[slot] = t;
        g_tokslot[t*TOPK + k] = slot;
    }
}

__global__ void combine_kernel(float* __restrict__ out) {
    int t = blockIdx.x, tid = threadIdx.x;
    int s0 = g_tokslot[t*TOPK + 0], s1 = g_tokslot[t*TOPK + 1];
    int s2 = g_tokslot[t*TOPK + 2], s3 = g_tokslot[t*TOPK + 3];
    float w0 = g_w[t*TOPK + 0], w1 = g_w[t*TOPK + 1];
    float w2 = g_w[t*TOPK + 2], w3 = g_w[t*TOPK + 3];
    const float4* sh4 = (const float4*)(g_shared + (size_t)t*H);
    const float4* y0 = (const float4*)(g_y + (size_t)s0*H);
    const float4* y1 = (const float4*)(g_y + (size_t)s1*H);
    const float4* y2 = (const float4*)(g_y + (size_t)s2*H);
    const float4* y3 = (const float4*)(g_y + (size_t)s3*H);
    float4* o4 = (float4*)(out + (size_t)t*H);
    int c = tid;
    float4 a = sh4[c], v0 = y0[c], v1 = y1[c], v2 = y2[c], v3 = y3[c];
    o4[c] = make_float4(
        a.x + w0*v0.x + w1*v1.x + w2*v2.x + w3*v3.x,
        a.y + w0*v0.y + w1*v1.y + w2*v2.y + w3*v3.y,
        a.z + w0*v0.z + w1*v1.z + w2*v2.z + w3*v3.z,
        a.w + w0*v0.w + w1*v1.w + w2*v2.w + w3*v3.w);
}

// ---------------- host orchestration -----------------------------------------
extern "C" void kernel_launch(void* const* d_in, const int* in_sizes, int n_in,
                              void* d_out, int out_size) {
    const float* hidden   = (const float*)d_in[0];
    const float* residual = (const float*)d_in[1];
    const float* in_ln_w  = (const float*)d_in[2];
    const float* post_ln_w= (const float*)d_in[3];
    const float* q_norm_w = (const float*)d_in[4];
    const float* k_norm_w = (const float*)d_in[5];
    const float* Wqkv     = (const float*)d_in[6];
    const float* Wo       = (const float*)d_in[7];
    const float* Wg       = (const float*)d_in[8];
    const float* gate_bias= (const float*)d_in[9];
    const float* Wgu      = (const float*)d_in[10];
    const float* Wd       = (const float*)d_in[11];
    const float* Wgu_sh   = (const float*)d_in[12];
    const float* Wd_sh    = (const float*)d_in[13];
    const int*   positions= (const int*)d_in[14];
    float* out = (float*)d_out;

    float *p_res1, *p_qkv, *p_attno, *p_h, *p_x2, *p_gu, *p_y, *p_gus, *p_shared;
    bf16 *p_xhi, *p_xlo, *p_x2hi, *p_x2lo, *p_aohi, *p_aolo;
    bf16 *p_acthi, *p_actlo, *p_actshi, *p_actslo, *p_qkvhi, *p_qkvlo;
    bf16 *p_wqkvhi, *p_wqkvlo, *p_wohi, *p_wolo, *p_wguhi, *p_wgulo;
    bf16 *p_wdhi, *p_wdlo, *p_wgushi, *p_wguslo, *p_wdshi, *p_wdslo;

    cudaGetSymbolAddress((void**)&p_res1,  g_res1);
    cudaGetSymbolAddress((void**)&p_qkv,   g_qkv);
    cudaGetSymbolAddress((void**)&p_attno, g_attno);
    cudaGetSymbolAddress((void**)&p_h,     g_h);
    cudaGetSymbolAddress((void**)&p_x2,    g_x2);
    cudaGetSymbolAddress((void**)&p_gu,    g_gu);
    cudaGetSymbolAddress((void**)&p_y,     g_y);
    cudaGetSymbolAddress((void**)&p_gus,   g_gus);
    cudaGetSymbolAddress((void**)&p_shared,g_shared);
    cudaGetSymbolAddress((void**)&p_xhi,   g_xhi);
    cudaGetSymbolAddress((void**)&p_xlo,   g_xlo);
    cudaGetSymbolAddress((void**)&p_x2hi,  g_x2hi);
    cudaGetSymbolAddress((void**)&p_x2lo,  g_x2lo);
    cudaGetSymbolAddress((void**)&p_aohi,  g_aohi);
    cudaGetSymbolAddress((void**)&p_aolo,  g_aolo);
    cudaGetSymbolAddress((void**)&p_acthi, g_acthi);
    cudaGetSymbolAddress((void**)&p_actlo, g_actlo);
    cudaGetSymbolAddress((void**)&p_actshi,g_actshi);
    cudaGetSymbolAddress((void**)&p_actslo,g_actslo);
    cudaGetSymbolAddress((void**)&p_qkvhi, g_qkvhi);
    cudaGetSymbolAddress((void**)&p_qkvlo, g_qkvlo);
    cudaGetSymbolAddress((void**)&p_wqkvhi,g_wqkvhi);
    cudaGetSymbolAddress((void**)&p_wqkvlo,g_wqkvlo);
    cudaGetSymbolAddress((void**)&p_wohi,  g_wohi);
    cudaGetSymbolAddress((void**)&p_wolo,  g_wolo);
    cudaGetSymbolAddress((void**)&p_wguhi, g_wguhi);
    cudaGetSymbolAddress((void**)&p_wgulo, g_wgulo);
    cudaGetSymbolAddress((void**)&p_wdhi,  g_wdhi);
    cudaGetSymbolAddress((void**)&p_wdlo,  g_wdlo);
    cudaGetSymbolAddress((void**)&p_wgushi,g_wgushi);
    cudaGetSymbolAddress((void**)&p_wguslo,g_wguslo);
    cudaGetSymbolAddress((void**)&p_wdshi, g_wdshi);
    cudaGetSymbolAddress((void**)&p_wdslo, g_wdslo);

    cudaFuncSetAttribute(tc_gemm, cudaFuncAttributeMaxDynamicSharedMemorySize, GSM_TOTAL);
    cudaFuncSetAttribute(tc_attn, cudaFuncAttributeMaxDynamicSharedMemorySize, ASM_TOTAL);

    dim3 wblk(32, 8);

    // 1. residual1 = hidden + residual ; x = rms(...) -> bf16 split only
    add_rmsnorm_kernel<<<T, 256>>>(hidden, residual, p_res1, in_ln_w, nullptr, p_xhi, p_xlo);

    // 2. qkv = x @ Wqkv
    wsplitT<<<dim3(QKVW/32, H/32, 1), wblk>>>(Wqkv, p_wqkvhi, p_wqkvlo, H, QKVW);
    tc_gemm<<<dim3(QKVW/128, T/128), 256, GSM_TOTAL>>>(p_xhi, p_xlo, p_wqkvhi, p_wqkvlo,
                                                       p_qkv, QKVW, H, 0, 0);

    // 3. q/k rmsnorm + rope, then split full qkv to bf16 hi/lo
    qknorm_rope_kernel<<<(T*(NH+NKV))/8, 256>>>(q_norm_w, k_norm_w, positions);
    split_kernel<<<(T*QKVW/4 + 255)/256, 256>>>(p_qkv, p_qkvhi, p_qkvlo, T*QKVW);

    // 4. attention (tensor cores)
    tc_attn<<<dim3(T/128, NH), 256, ASM_TOTAL>>>();

    // 5. h = attno @ Wo ; residual2 -> out ; x2 = rms(residual2)
    split_kernel<<<(T*H/4 + 255)/256, 256>>>(p_attno, p_aohi, p_aolo, T*H);
    wsplitT<<<dim3(H/32, H/32, 1), wblk>>>(Wo, p_wohi, p_wolo, H, H);
    tc_gemm<<<dim3(H/128, T/128), 256, GSM_TOTAL>>>(p_aohi, p_aolo, p_wohi, p_wolo,
                                                    p_h, H, H, 0, 0);
    float* out_res = out + (size_t)T*H;
    add_rmsnorm_kernel<<<T, 256>>>(p_h, p_res1, out_res, post_ln_w, p_x2, p_x2hi, p_x2lo);

    // 6. router + dispatch
    zero_kernel<<<1, 32>>>();
    router_kernel<<<T, 32>>>(Wg, gate_bias);
    scan_kernel<<<1, 1>>>();
    scatter_kernel<<<(T + 255)/256, 256>>>();

    // 7. routed experts
    wsplitT<<<dim3(2*IM/32, H/32, E), wblk>>>(Wgu, p_wguhi, p_wgulo, H, 2*IM);
    tc_gemm<<<dim3(2*IM/128, NSLOT/128, E), 256, GSM_TOTAL>>>(p_x2hi, p_x2lo, p_wguhi, p_wgulo,
                                                              p_gu, 2*IM, H, 1, 1);
    silu_split<<<(NSLOT*IM + 255)/256, 256>>>(p_gu, p_acthi, p_actlo, NSLOT*IM);
    wsplitT<<<dim3(H/32, IM/32, E), wblk>>>(Wd, p_wdhi, p_wdlo, IM, H);
    tc_gemm<<<dim3(H/128, NSLOT/128, E), 256, GSM_TOTAL>>>(p_acthi, p_actlo, p_wdhi, p_wdlo,
                                                           p_y, H, IM, 1, 0);

    // 8. shared expert
    wsplitT<<<dim3(2*IM/32, H/32, 1), wblk>>>(Wgu_sh, p_wgushi, p_wguslo, H, 2*IM);
    tc_gemm<<<dim3(2*IM/128, T/128), 256, GSM_TOTAL>>>(p_x2hi, p_x2lo, p_wgushi, p_wguslo,
                                                       p_gus, 2*IM, H, 0, 0);
    silu_split<<<(T*IM + 255)/256, 256>>>(p_gus, p_actshi, p_actslo, T*IM);
    wsplitT<<<dim3(H/32, IM/32, 1), wblk>>>(Wd_sh, p_wdshi, p_wdslo, IM, H);
    tc_gemm<<<dim3(H/128, T/128), 256, GSM_TOTAL>>>(p_actshi, p_actslo, p_wdshi, p_wdslo,
                                                    p_shared, H, IM, 0, 0);

    // 9. combine
    combine_kernel<<<T, 256>>>(out);
}

// round 16
// speedup vs baseline: 1.5694x; 1.0247x over previous
#include <cuda_runtime.h>
#include <cuda_bf16.h>
#include <math.h>
#include <stdint.h>

#define T 2048
#define H 1024
#define NH 16
#define NKV 4
#define HD 64
#define E 32
#define TOPK 4
#define IM 384
#define QKVW 1536   // (NH + 2*NKV) * HD
#define NSLOT (T*TOPK)

typedef __nv_bfloat16 bf16;

// ---------------- scratch (device globals; no allocation allowed) ------------
__device__ float g_res1[T*H];
__device__ float g_qkv[T*QKVW];
__device__ float g_h[T*H];
__device__ float g_x2[T*H];
__device__ float g_gu[NSLOT*2*IM];
__device__ float g_y[(size_t)NSLOT*H];
__device__ float g_gus[T*2*IM];
__device__ float g_shared[T*H];
__device__ int   g_ids[T*TOPK];
__device__ float g_w[T*TOPK];
__device__ int   g_cnt[E];
__device__ int   g_off[E];
__device__ int   g_fill[E];
__device__ int   g_slot2tok[NSLOT];
__device__ int   g_tokslot[T*TOPK];

// bf16 split activations
__device__ bf16 g_xhi[T*H],   g_xlo[T*H];
__device__ bf16 g_x2hi[T*H],  g_x2lo[T*H];
__device__ bf16 g_aohi[T*H],  g_aolo[T*H];
__device__ bf16 g_acthi[NSLOT*IM],  g_actlo[NSLOT*IM];
__device__ bf16 g_actshi[T*IM],     g_actslo[T*IM];
__device__ bf16 g_qkvhi[(size_t)T*QKVW], g_qkvlo[(size_t)T*QKVW];
// bf16 split + transposed weights ([N,K] layout, per-expert contiguous)
__device__ bf16 g_wqkvhi[(size_t)QKVW*H], g_wqkvlo[(size_t)QKVW*H];
__device__ bf16 g_wohi[(size_t)H*H],      g_wolo[(size_t)H*H];
__device__ bf16 g_wguhi[(size_t)E*2*IM*H], g_wgulo[(size_t)E*2*IM*H];
__device__ bf16 g_wdhi[(size_t)E*H*IM],    g_wdlo[(size_t)E*H*IM];
__device__ bf16 g_wgushi[(size_t)2*IM*H],  g_wguslo[(size_t)2*IM*H];
__device__ bf16 g_wdshi[(size_t)H*IM],     g_wdslo[(size_t)H*IM];

__device__ __forceinline__ uint32_t smem_u32(const void* p) {
    uint32_t a;
    asm("{ .reg .u64 t; cvta.to.shared.u64 t, %1; cvt.u32.u64 %0, t; }" : "=r"(a) : "l"(p));
    return a;
}

#define CP8(s, g, sz) \
    asm volatile("cp.async.ca.shared.global [%0], [%1], 8, %2;" :: "r"(s), "l"(g), "r"(sz))
#define CP16(s, g) \
    asm volatile("cp.async.cg.shared.global [%0], [%1], 16;" :: "r"(s), "l"(g))
#define CP_COMMIT() asm volatile("cp.async.commit_group;" ::: "memory")
#define CP_WAIT1()  asm volatile("cp.async.wait_group 1;" ::: "memory")
#define CP_WAIT0()  asm volatile("cp.async.wait_group 0;" ::: "memory")

#define MMA_BF16(c, a, b) \
    asm volatile("mma.sync.aligned.m16n8k16.row.col.f32.bf16.bf16.f32 " \
        "{%0,%1,%2,%3}, {%4,%5,%6,%7}, {%8,%9}, {%0,%1,%2,%3};" \
        : "+f"((c)[0]), "+f"((c)[1]), "+f"((c)[2]), "+f"((c)[3]) \
        : "r"((a)[0]), "r"((a)[1]), "r"((a)[2]), "r"((a)[3]), "r"((b)[0]), "r"((b)[1]))

#define LDSM4(r, a) \
    asm volatile("ldmatrix.sync.aligned.m8n8.x4.shared.b16 {%0,%1,%2,%3}, [%4];" \
        : "=r"((r)[0]), "=r"((r)[1]), "=r"((r)[2]), "=r"((r)[3]) : "r"(a))

__device__ __forceinline__ uint32_t packbf2(float a, float b) {
    __nv_bfloat162 t = __floats2bfloat162_rn(a, b);
    return *(uint32_t*)&t;
}

// ======================= tensor-core GEMM (mma.sync + ldmatrix) ==============
#define GP 40
#define TILE_B (128*GP*2)
#define OFF_ALO (1*TILE_B)
#define OFF_BHI (2*TILE_B)
#define OFF_BLO (3*TILE_B)
#define CHUNK_B (4*TILE_B)
#define GSM_TOTAL (2*CHUNK_B)

__global__ __launch_bounds__(256) void tc_gemm(
    const bf16* __restrict__ Ahi, const bf16* __restrict__ Alo,
    const bf16* __restrict__ Bhi, const bf16* __restrict__ Blo,
    float* __restrict__ C, int N, int K, int moe, int gather)
{
    extern __shared__ __align__(16) char dsm[];
    int tid = threadIdx.x;
    int warp = tid >> 5, lane = tid & 31;
    int wm = warp & 1, wn = warp >> 1;
    int g = lane >> 2, t2 = (lane & 3) * 2;
    int bn = blockIdx.x * 128;
    int bm = blockIdx.y * 128;

    int cnt = 0, basem = 0;
    const bf16* bh = Bhi; const bf16* bl = Blo;
    if (moe) {
        int e = blockIdx.z;
        cnt = g_cnt[e];
        if (bm >= cnt) return;
        basem = g_off[e];
        size_t ws = (size_t)N * K;
        bh += ws * (size_t)e; bl += ws * (size_t)e;
    }

    int r = tid >> 1, h = tid & 1;
    long arow;
    uint32_t asz = 8;
    if (moe) {
        int rr = bm + r;
        if (rr < cnt) arow = gather ? (long)g_slot2tok[basem + rr] : (long)(basem + rr);
        else { arow = 0; asz = 0; }
    } else arow = bm + r;
    long brow = bn + r;

    uint32_t sbase = smem_u32(dsm);
    uint32_t srow = (uint32_t)(r * GP + h * 16) * 2;

    // ldmatrix per-thread fragment byte offsets (within a tile)
    uint32_t aFrag = (uint32_t)((wm*64 + (lane & 15)) * GP + ((lane >> 4) << 3)) * 2;
    uint32_t bFrag = (uint32_t)((wn*32 + (lane & 7) + ((lane >> 4) << 3)) * GP
                                + (((lane >> 3) & 1) << 3)) * 2;

    auto prefetch = [&](int c, int b) {
        size_t ka = (size_t)c * 32 + h * 16;
        uint32_t sb = sbase + b * CHUNK_B + srow;
        const bf16* gah = Ahi + arow * K + ka;
        const bf16* gal = Alo + arow * K + ka;
        const bf16* gbh = bh + brow * K + ka;
        const bf16* gbl = bl + brow * K + ka;
        #pragma unroll
        for (int i = 0; i < 4; i++) {
            CP8(sb + i*8,           gah + i*4, asz);
            CP8(sb + OFF_ALO + i*8, gal + i*4, asz);
            CP8(sb + OFF_BHI + i*8, gbh + i*4, 8u);
            CP8(sb + OFF_BLO + i*8, gbl + i*4, 8u);
        }
    };

    float acc[4][4][4];
    #pragma unroll
    for (int mi = 0; mi < 4; mi++)
        #pragma unroll
        for (int ni = 0; ni < 4; ni++)
            #pragma unroll
            for (int q = 0; q < 4; q++) acc[mi][ni][q] = 0.f;

    int NC = K / 32;
    prefetch(0, 0);
    CP_COMMIT();

    for (int c = 0; c < NC; c++) {
        int b = c & 1;
        if (c + 1 < NC) prefetch(c + 1, b ^ 1);
        CP_COMMIT();
        CP_WAIT1();
        __syncthreads();

        uint32_t tb = sbase + b * CHUNK_B;

        #pragma unroll
        for (int ks = 0; ks < 2; ks++) {
            uint32_t koB = (uint32_t)ks * 32;
            uint32_t ah[4][4], al[4][4], bh4[2][4], bl4[2][4];
            #pragma unroll
            for (int mi = 0; mi < 4; mi++) {
                uint32_t ao = tb + aFrag + (uint32_t)mi * (16*GP*2) + koB;
                LDSM4(ah[mi], ao);
                LDSM4(al[mi], ao + OFF_ALO);
            }
            #pragma unroll
            for (int nip = 0; nip < 2; nip++) {
                uint32_t bo = tb + OFF_BHI + bFrag + (uint32_t)nip * (16*GP*2) + koB;
                LDSM4(bh4[nip], bo);
                LDSM4(bl4[nip], bo + TILE_B);
            }
            #pragma unroll
            for (int mi = 0; mi < 4; mi++)
                #pragma unroll
                for (int ni = 0; ni < 4; ni++) {
                    uint32_t* bhp = &bh4[ni >> 1][(ni & 1) * 2];
                    uint32_t* blp = &bl4[ni >> 1][(ni & 1) * 2];
                    MMA_BF16(acc[mi][ni], ah[mi], bhp);
                    MMA_BF16(acc[mi][ni], ah[mi], blp);
                    MMA_BF16(acc[mi][ni], al[mi], bhp);
                }
        }
        __syncthreads();
    }

    #pragma unroll
    for (int mi = 0; mi < 4; mi++) {
        int lr0 = bm + wm * 64 + mi * 16 + g;
        int lr1 = lr0 + 8;
        bool v0 = moe ? (lr0 < cnt) : true;
        bool v1 = moe ? (lr1 < cnt) : true;
        size_t ro0 = ((size_t)(moe ? basem : 0) + lr0) * N;
        size_t ro1 = ((size_t)(moe ? basem : 0) + lr1) * N;
        #pragma unroll
        for (int ni = 0; ni < 4; ni++) {
            int col = bn + wn * 32 + ni * 8 + t2;
            if (v0) *(float2*)&C[ro0 + col] = make_float2(acc[mi][ni][0], acc[mi][ni][1]);
            if (v1) *(float2*)&C[ro1 + col] = make_float2(acc[mi][ni][2], acc[mi][ni][3]);
        }
    }
}

// ================= tensor-core flash attention ===============================
// One CTA per (q-tile of 128, head). 8 warps x 16 q-rows. K/V tiles of 64.
// Epilogue writes bf16 hi/lo directly (consumed by the Wo GEMM).
#define AP 72
#define ASM_TOTAL ((128*2 + 64*4)*AP*2)   // bytes

__global__ __launch_bounds__(256) void tc_attn() {
    extern __shared__ __align__(16) bf16 smA[];
    bf16* Qhi = smA;
    bf16* Qlo = Qhi + 128*AP;
    bf16* Khi = Qlo + 128*AP;
    bf16* Klo = Khi + 64*AP;
    bf16* Vhi = Klo + 64*AP;   // transposed: [dim][key]
    bf16* Vlo = Vhi + 64*AP;

    int h = blockIdx.y;
    int qt = (int)gridDim.x - 1 - (int)blockIdx.x;   // big tiles first
    int q0 = qt * 128;
    int kvh = h >> 2;
    int tid = threadIdx.x, warp = tid >> 5, lane = tid & 31;
    int g = lane >> 2, t2 = (lane & 3) * 2;

    // ---- load Q tile (hi/lo), 128 rows x 64 dims
    {
        int r = tid >> 1, hf = tid & 1;
        const bf16* sh = g_qkvhi + (size_t)(q0 + r)*QKVW + h*HD + hf*32;
        const bf16* sl = g_qkvlo + (size_t)(q0 + r)*QKVW + h*HD + hf*32;
        uint32_t dh = smem_u32(Qhi + r*AP + hf*32);
        uint32_t dl = smem_u32(Qlo + r*AP + hf*32);
        #pragma unroll
        for (int i = 0; i < 4; i++) { CP16(dh + i*16, sh + i*8); CP16(dl + i*16, sl + i*8); }
    }
    CP_COMMIT(); CP_WAIT0(); __syncthreads();

    // preload Q fragments (registers, reused across all k-tiles)
    uint32_t qh[4][4], ql[4][4];
    {
        int qrow = warp*16 + g;
        #pragma unroll
        for (int ks = 0; ks < 4; ks++) {
            int ko = ks * 16;
            qh[ks][0] = *(const uint32_t*)&Qhi[qrow*AP + ko + t2];
            qh[ks][1] = *(const uint32_t*)&Qhi[(qrow+8)*AP + ko + t2];
            qh[ks][2] = *(const uint32_t*)&Qhi[qrow*AP + ko + t2 + 8];
            qh[ks][3] = *(const uint32_t*)&Qhi[(qrow+8)*AP + ko + t2 + 8];
            ql[ks][0] = *(const uint32_t*)&Qlo[qrow*AP + ko + t2];
            ql[ks][1] = *(const uint32_t*)&Qlo[(qrow+8)*AP + ko + t2];
            ql[ks][2] = *(const uint32_t*)&Qlo[qrow*AP + ko + t2 + 8];
            ql[ks][3] = *(const uint32_t*)&Qlo[(qrow+8)*AP + ko + t2 + 8];
        }
    }

    float accO[8][4];
    #pragma unroll
    for (int od = 0; od < 8; od++)
        #pragma unroll
        for (int q = 0; q < 4; q++) accO[od][q] = 0.f;
    float m0 = -INFINITY, m1 = -INFINITY, l0 = 0.f, l1 = 0.f;
    int r0 = q0 + warp*16 + g, r1 = r0 + 8;

    int ntiles = 2*qt + 2;
    for (int jt = 0; jt < ntiles; jt++) {
        int k0 = jt * 64;
        // load K tile (hi/lo) [key][dim]
        {
            int r = tid >> 2, q4 = tid & 3;
            const bf16* sh = g_qkvhi + (size_t)(k0 + r)*QKVW + NH*HD + kvh*HD + q4*16;
            const bf16* sl = g_qkvlo + (size_t)(k0 + r)*QKVW + NH*HD + kvh*HD + q4*16;
            uint32_t dh = smem_u32(Khi + r*AP + q4*16);
            uint32_t dl = smem_u32(Klo + r*AP + q4*16);
            CP16(dh, sh); CP16(dh + 16, sh + 8);
            CP16(dl, sl); CP16(dl + 16, sl + 8);
        }
        // load V tile transposed -> [dim][key]
        {
            int vr = tid >> 2, vq = (tid & 3) * 8;
            const uint32_t* ph = (const uint32_t*)(g_qkvhi + (size_t)(k0 + vr)*QKVW + (NH+NKV)*HD + kvh*HD) + vq;
            const uint32_t* pl = (const uint32_t*)(g_qkvlo + (size_t)(k0 + vr)*QKVW + (NH+NKV)*HD + kvh*HD) + vq;
            #pragma unroll
            for (int j = 0; j < 8; j++) {
                uint32_t wh = ph[j], wl = pl[j];
                int d0 = 2*(vq + j);
                __nv_bfloat162 vh = *(__nv_bfloat162*)&wh;
                __nv_bfloat162 vl = *(__nv_bfloat162*)&wl;
                Vhi[d0*AP + vr] = vh.x; Vhi[(d0+1)*AP + vr] = vh.y;
                Vlo[d0*AP + vr] = vl.x; Vlo[(d0+1)*AP + vr] = vl.y;
            }
        }
        CP_COMMIT(); CP_WAIT0(); __syncthreads();

        // ---- S = Q @ K^T (3-term split)
        float s[8][4];
        #pragma unroll
        for (int nb = 0; nb < 8; nb++)
            #pragma unroll
            for (int q = 0; q < 4; q++) s[nb][q] = 0.f;
        #pragma unroll
        for (int ks = 0; ks < 4; ks++) {
            int ko = ks * 16;
            #pragma unroll
            for (int nb = 0; nb < 8; nb++) {
                int nr = nb*8 + g;
                uint32_t bh[2], bl[2];
                bh[0] = *(const uint32_t*)&Khi[nr*AP + ko + t2];
                bh[1] = *(const uint32_t*)&Khi[nr*AP + ko + t2 + 8];
                bl[0] = *(const uint32_t*)&Klo[nr*AP + ko + t2];
                bl[1] = *(const uint32_t*)&Klo[nr*AP + ko + t2 + 8];
                MMA_BF16(s[nb], qh[ks], bh);
                MMA_BF16(s[nb], qh[ks], bl);
                MMA_BF16(s[nb], ql[ks], bh);
            }
        }
        // scale + causal mask
        #pragma unroll
        for (int nb = 0; nb < 8; nb++)
            #pragma unroll
            for (int q = 0; q < 4; q++) s[nb][q] *= 0.125f;
        if (jt >= 2*qt) {
            #pragma unroll
            for (int nb = 0; nb < 8; nb++) {
                int c0 = k0 + nb*8 + t2, c1 = c0 + 1;
                if (c0 > r0) s[nb][0] = -INFINITY;
                if (c1 > r0) s[nb][1] = -INFINITY;
                if (c0 > r1) s[nb][2] = -INFINITY;
                if (c1 > r1) s[nb][3] = -INFINITY;
            }
        }
        // ---- online softmax
        float mx0 = -INFINITY, mx1 = -INFINITY;
        #pragma unroll
        for (int nb = 0; nb < 8; nb++) {
            mx0 = fmaxf(mx0, fmaxf(s[nb][0], s[nb][1]));
            mx1 = fmaxf(mx1, fmaxf(s[nb][2], s[nb][3]));
        }
        mx0 = fmaxf(mx0, __shfl_xor_sync(0xffffffffu, mx0, 1));
        mx0 = fmaxf(mx0, __shfl_xor_sync(0xffffffffu, mx0, 2));
        mx1 = fmaxf(mx1, __shfl_xor_sync(0xffffffffu, mx1, 1));
        mx1 = fmaxf(mx1, __shfl_xor_sync(0xffffffffu, mx1, 2));
        float mn0 = fmaxf(m0, mx0), mn1 = fmaxf(m1, mx1);
        float al0 = __expf(m0 - mn0), al1 = __expf(m1 - mn1);
        m0 = mn0; m1 = mn1;
        float ps0 = 0.f, ps1 = 0.f;
        #pragma unroll
        for (int nb = 0; nb < 8; nb++) {
            s[nb][0] = __expf(s[nb][0] - mn0); ps0 += s[nb][0];
            s[nb][1] = __expf(s[nb][1] - mn0); ps0 += s[nb][1];
            s[nb][2] = __expf(s[nb][2] - mn1); ps1 += s[nb][2];
            s[nb][3] = __expf(s[nb][3] - mn1); ps1 += s[nb][3];
        }
        l0 = l0*al0 + ps0; l1 = l1*al1 + ps1;
        #pragma unroll
        for (int od = 0; od < 8; od++) {
            accO[od][0] *= al0; accO[od][1] *= al0;
            accO[od][2] *= al1; accO[od][3] *= al1;
        }
        // ---- O += P @ V (3-term split, P repacked from S accumulators)
        #pragma unroll
        for (int ks = 0; ks < 4; ks++) {
            uint32_t aph[4], apl[4];
            #pragma unroll
            for (int half = 0; half < 2; half++) {
                int nb = 2*ks + half;
                float p0 = s[nb][0], p1 = s[nb][1], p2 = s[nb][2], p3 = s[nb][3];
                bf16 h0 = __float2bfloat16(p0), h1 = __float2bfloat16(p1);
                bf16 h2 = __float2bfloat16(p2), h3 = __float2bfloat16(p3);
                __nv_bfloat162 t01; t01.x = h0; t01.y = h1;
                aph[half*2 + 0] = *(uint32_t*)&t01;
                __nv_bfloat162 t23; t23.x = h2; t23.y = h3;
                aph[half*2 + 1] = *(uint32_t*)&t23;
                apl[half*2 + 0] = packbf2(p0 - __bfloat162float(h0), p1 - __bfloat162float(h1));
                apl[half*2 + 1] = packbf2(p2 - __bfloat162float(h2), p3 - __bfloat162float(h3));
            }
            int ko = ks * 16;
            #pragma unroll
            for (int od = 0; od < 8; od++) {
                int nr = od*8 + g;
                uint32_t bh[2], bl[2];
                bh[0] = *(const uint32_t*)&Vhi[nr*AP + ko + t2];
                bh[1] = *(const uint32_t*)&Vhi[nr*AP + ko + t2 + 8];
                bl[0] = *(const uint32_t*)&Vlo[nr*AP + ko + t2];
                bl[1] = *(const uint32_t*)&Vlo[nr*AP + ko + t2 + 8];
                MMA_BF16(accO[od], aph, bh);
                MMA_BF16(accO[od], aph, bl);
                MMA_BF16(accO[od], apl, bh);
            }
        }
        __syncthreads();   // K/V smem reused next tile
    }

    // final: reduce l across quad, divide, store bf16 hi/lo directly
    l0 += __shfl_xor_sync(0xffffffffu, l0, 1);
    l0 += __shfl_xor_sync(0xffffffffu, l0, 2);
    l1 += __shfl_xor_sync(0xffffffffu, l1, 1);
    l1 += __shfl_xor_sync(0xffffffffu, l1, 2);
    float inv0 = 1.f / l0, inv1 = 1.f / l1;
    #pragma unroll
    for (int od = 0; od < 8; od++) {
        int col = h*HD + od*8 + t2;
        float o0 = accO[od][0]*inv0, o1 = accO[od][1]*inv0;
        float o2 = accO[od][2]*inv1, o3 = accO[od][3]*inv1;
        bf16 h0 = __float2bfloat16(o0), h1 = __float2bfloat16(o1);
        bf16 h2 = __float2bfloat16(o2), h3 = __float2bfloat16(o3);
        __nv_bfloat162 hp0; hp0.x = h0; hp0.y = h1;
        __nv_bfloat162 hp1; hp1.x = h2; hp1.y = h3;
        *(__nv_bfloat162*)&g_aohi[(size_t)r0*H + col] = hp0;
        *(__nv_bfloat162*)&g_aohi[(size_t)r1*H + col] = hp1;
        uint32_t lp0 = packbf2(o0 - __bfloat162float(h0), o1 - __bfloat162float(h1));
        uint32_t lp1 = packbf2(o2 - __bfloat162float(h2), o3 - __bfloat162float(h3));
        *(uint32_t*)&g_aolo[(size_t)r0*H + col] = lp0;
        *(uint32_t*)&g_aolo[(size_t)r1*H + col] = lp1;
    }
}

// ===================== conversion kernels ====================================
// split V columns of qkv only (Q/K are split inside qknorm_rope)
__global__ void vsplit_kernel() {
    int t = blockIdx.x, tid = threadIdx.x;   // 64 threads x 4 elems = 256 cols
    size_t base = (size_t)t*QKVW + (NH+NKV)*HD;
    float4 v = *(const float4*)(g_qkv + base + tid*4);
    bf16 h0 = __float2bfloat16(v.x), h1 = __float2bfloat16(v.y);
    bf16 h2 = __float2bfloat16(v.z), h3 = __float2bfloat16(v.w);
    __nv_bfloat162* Hp = (__nv_bfloat162*)(g_qkvhi + base + tid*4);
    __nv_bfloat162* Lp = (__nv_bfloat162*)(g_qkvlo + base + tid*4);
    Hp[0] = __halves2bfloat162(h0, h1); Hp[1] = __halves2bfloat162(h2, h3);
    Lp[0] = __halves2bfloat162(__float2bfloat16(v.x - __bfloat162float(h0)),
                               __float2bfloat16(v.y - __bfloat162float(h1)));
    Lp[1] = __halves2bfloat162(__float2bfloat16(v.z - __bfloat162float(h2)),
                               __float2bfloat16(v.w - __bfloat162float(h3)));
}

__global__ void wsplitT(const float* __restrict__ W, bf16* __restrict__ hi,
                        bf16* __restrict__ lo, int K, int N) {
    size_t ws = (size_t)K * N * blockIdx.z;
    const float* Wp = W + ws;
    bf16* hp = hi + ws; bf16* lp = lo + ws;
    __shared__ float tl[32][33];
    int n0 = blockIdx.x * 32, k0 = blockIdx.y * 32;
    int tx = threadIdx.x, ty = threadIdx.y;
    #pragma unroll
    for (int j = 0; j < 4; j++) {
        int k = ty + j * 8;
        tl[k][tx] = Wp[(size_t)(k0 + k) * N + n0 + tx];
    }
    __syncthreads();
    #pragma unroll
    for (int j = 0; j < 4; j++) {
        int nl = ty + j * 8;
        float v = tl[tx][nl];
        bf16 h = __float2bfloat16(v);
        size_t o = (size_t)(n0 + nl) * K + k0 + tx;
        hp[o] = h;
        lp[o] = __float2bfloat16(v - __bfloat162float(h));
    }
}

__global__ void add_rmsnorm_kernel(const float* __restrict__ a, const float* __restrict__ b,
                                   float* __restrict__ res, const float* __restrict__ w,
                                   float* __restrict__ y, bf16* __restrict__ yhi,
                                   bf16* __restrict__ ylo) {
    int t = blockIdx.x, tid = threadIdx.x;
    __shared__ float red[256];
    const float4* a4 = (const float4*)(a + (size_t)t * H);
    const float4* b4 = (const float4*)(b + (size_t)t * H);
    float4 va = a4[tid], vb = b4[tid];
    float4 v = make_float4(va.x + vb.x, va.y + vb.y, va.z + vb.z, va.w + vb.w);
    ((float4*)(res + (size_t)t * H))[tid] = v;
    float s = v.x*v.x + v.y*v.y + v.z*v.z + v.w*v.w;
    red[tid] = s; __syncthreads();
    for (int o = 128; o; o >>= 1) { if (tid < o) red[tid] += red[tid + o]; __syncthreads(); }
    float inv = rsqrtf(red[0] / (float)H + 1e-5f);
    float4 wv = ((const float4*)w)[tid];
    float4 o4 = make_float4(v.x*inv*wv.x, v.y*inv*wv.y, v.z*inv*wv.z, v.w*inv*wv.w);
    if (y) ((float4*)(y + (size_t)t * H))[tid] = o4;
    bf16 h0 = __float2bfloat16(o4.x), h1 = __float2bfloat16(o4.y);
    bf16 h2 = __float2bfloat16(o4.z), h3 = __float2bfloat16(o4.w);
    bf16 l0 = __float2bfloat16(o4.x - __bfloat162float(h0));
    bf16 l1 = __float2bfloat16(o4.y - __bfloat162float(h1));
    bf16 l2 = __float2bfloat16(o4.z - __bfloat162float(h2));
    bf16 l3 = __float2bfloat16(o4.w - __bfloat162float(h3));
    __nv_bfloat162* Hp = (__nv_bfloat162*)(yhi + (size_t)t * H) + tid * 2;
    __nv_bfloat162* Lp = (__nv_bfloat162*)(ylo + (size_t)t * H) + tid * 2;
    Hp[0] = __halves2bfloat162(h0, h1); Hp[1] = __halves2bfloat162(h2, h3);
    Lp[0] = __halves2bfloat162(l0, l1); Lp[1] = __halves2bfloat162(l2, l3);
}

__global__ void silu_split(const float* __restrict__ gu, bf16* __restrict__ hi,
                           bf16* __restrict__ lo, int total) {
    int i = blockIdx.x * blockDim.x + threadIdx.x;
    if (i >= total) return;
    int r = i / IM, c = i % IM;
    float g = gu[(size_t)r*2*IM + c], u = gu[(size_t)r*2*IM + IM + c];
    float a = g * (1.f / (1.f + expf(-g))) * u;
    bf16 h = __float2bfloat16(a);
    hi[i] = h;
    lo[i] = __float2bfloat16(a - __bfloat162float(h));
}

// ------- Q/K rmsnorm + RoPE, writing bf16 hi/lo directly (no fp32 out) -------
__global__ void qknorm_rope_kernel(const float* __restrict__ qw, const float* __restrict__ kw,
                                   const int* __restrict__ pos) {
    int idx = blockIdx.x * 8 + (threadIdx.x >> 5);
    if (idx >= T * (NH + NKV)) return;
    int t = idx / (NH + NKV), hh = idx % (NH + NKV);
    size_t gbase;
    const float* w;
    if (hh < NH) { gbase = (size_t)t*QKVW + hh*HD; w = qw; }
    else         { gbase = (size_t)t*QKVW + NH*HD + (hh-NH)*HD; w = kw; }
    const float* v = g_qkv + gbase;
    int lane = threadIdx.x & 31;
    int warp = threadIdx.x >> 5;
    float a = v[lane], b = v[lane + 32];
    float ss = a*a + b*b;
    #pragma unroll
    for (int o = 16; o; o >>= 1) ss += __shfl_xor_sync(0xffffffffu, ss, o);
    float inv = rsqrtf(ss / (float)HD + 1e-5f);
    a *= inv * w[lane]; b *= inv * w[lane + 32];
    __shared__ float sh[8][64];
    sh[warp][lane] = a; sh[warp][lane + 32] = b;
    __syncwarp();
    float p = (float)pos[t];
    float val0, val1; int pos0, pos1;
    if (lane < 16) {
        float invf = expf(-((float)lane / 16.f) * logf(10000.f));
        float ang = p * invf;
        float c = cosf(ang), s = sinf(ang);
        float x1 = sh[warp][lane], x2 = sh[warp][lane + 16];
        val0 = x1*c - x2*s; pos0 = lane;
        val1 = x1*s + x2*c; pos1 = lane + 16;
    } else {
        val0 = sh[warp][lane + 16]; pos0 = lane + 16;
        val1 = sh[warp][lane + 32]; pos1 = lane + 32;
    }
    bf16 h0 = __float2bfloat16(val0);
    bf16 h1 = __float2bfloat16(val1);
    g_qkvhi[gbase + pos0] = h0;
    g_qkvlo[gbase + pos0] = __float2bfloat16(val0 - __bfloat162float(h0));
    g_qkvhi[gbase + pos1] = h1;
    g_qkvlo[gbase + pos1] = __float2bfloat16(val1 - __bfloat162float(h1));
}

// ---------------- router ------------------------------------------------------
__global__ void router_kernel(const float* __restrict__ Wg, const float* __restrict__ bias) {
    int t = blockIdx.x, tx = threadIdx.x;
    __shared__ float xs[H];
    __shared__ float scr[E], sfc[E];
    for (int hh = tx; hh < H; hh += 32) xs[hh] = g_x2[(size_t)t*H + hh];
    __syncthreads();
    float acc = 0.f;
    for (int hh = 0; hh < H; hh++) acc += xs[hh] * Wg[hh*E + tx];
    float sc = 1.f / (1.f + expf(-acc));
    scr[tx] = sc; sfc[tx] = sc + bias[tx];
    __syncthreads();
    if (tx == 0) {
        float gs[4];
        for (int g = 0; g < 4; g++) {
            float m1 = -INFINITY, m2 = -INFINITY;
            for (int j = 0; j < 8; j++) {
                float v = sfc[g*8 + j];
                if (v > m1) { m2 = m1; m1 = v; } else if (v > m2) m2 = v;
            }
            gs[g] = m1 + m2;
        }
        int g1 = 0;
        for (int g = 1; g < 4; g++) if (gs[g] > gs[g1]) g1 = g;
        int g2 = -1;
        for (int g = 0; g < 4; g++) { if (g == g1) continue; if (g2 < 0 || gs[g] > gs[g2]) g2 = g; }
        bool used[E];
        for (int e = 0; e < E; e++) used[e] = false;
        float wk[TOPK]; int idk[TOPK]; float wsum = 0.f;
        for (int k = 0; k < TOPK; k++) {
            int best = -1; float bv = -INFINITY;
            for (int e = 0; e < E; e++) {
                int g = e >> 3;
                if (g != g1 && g != g2) continue;
                if (used[e]) continue;
                if (sfc[e] > bv) { bv = sfc[e]; best = e; }
            }
            used[best] = true; idk[k] = best;
            wk[k] = scr[best]; wsum += wk[k];
        }
        for (int k = 0; k < TOPK; k++) {
            g_ids[t*TOPK + k] = idk[k];
            g_w[t*TOPK + k] = wk[k] / wsum;
            atomicAdd(&g_cnt[idk[k]], 1);
        }
    }
}

__global__ void zero_kernel() {
    int i = threadIdx.x;
    if (i < E) { g_cnt[i] = 0; g_fill[i] = 0; }
}

__global__ void scan_kernel() {
    if (threadIdx.x == 0) {
        int s = 0;
        for (int e = 0; e < E; e++) { g_off[e] = s; s += g_cnt[e]; }
    }
}

__global__ void scatter_kernel() {
    int t = blockIdx.x * blockDim.x + threadIdx.x;
    if (t >= T) return;
    for (int k = 0; k < TOPK; k++) {
        int e = g_ids[t*TOPK + k];
        int slot = g_off[e] + atomicAdd(&g_fill[e], 1);
        g_slot2tok[slot] = t;
        g_tokslot[t*TOPK + k] = slot;
    }
}

__global__ void combine_kernel(float* __restrict__ out) {
    int t = blockIdx.x, tid = threadIdx.x;
    int s0 = g_tokslot[t*TOPK + 0], s1 = g_tokslot[t*TOPK + 1];
    int s2 = g_tokslot[t*TOPK + 2], s3 = g_tokslot[t*TOPK + 3];
    float w0 = g_w[t*TOPK + 0], w1 = g_w[t*TOPK + 1];
    float w2 = g_w[t*TOPK + 2], w3 = g_w[t*TOPK + 3];
    const float4* sh4 = (const float4*)(g_shared + (size_t)t*H);
    const float4* y0 = (const float4*)(g_y + (size_t)s0*H);
    const float4* y1 = (const float4*)(g_y + (size_t)s1*H);
    const float4* y2 = (const float4*)(g_y + (size_t)s2*H);
    const float4* y3 = (const float4*)(g_y + (size_t)s3*H);
    float4* o4 = (float4*)(out + (size_t)t*H);
    int c = tid;
    float4 a = sh4[c], v0 = y0[c], v1 = y1[c], v2 = y2[c], v3 = y3[c];
    o4[c] = make_float4(
        a.x + w0*v0.x + w1*v1.x + w2*v2.x + w3*v3.x,
        a.y + w0*v0.y + w1*v1.y + w2*v2.y + w3*v3.y,
        a.z + w0*v0.z + w1*v1.z + w2*v2.z + w3*v3.z,
        a.w + w0*v0.w + w1*v1.w + w2*v2.w + w3*v3.w);
}

// ---------------- host orchestration -----------------------------------------
extern "C" void kernel_launch(void* const* d_in, const int* in_sizes, int n_in,
                              void* d_out, int out_size) {
    const float* hidden   = (const float*)d_in[0];
    const float* residual = (const float*)d_in[1];
    const float* in_ln_w  = (const float*)d_in[2];
    const float* post_ln_w= (const float*)d_in[3];
    const float* q_norm_w = (const float*)d_in[4];
    const float* k_norm_w = (const float*)d_in[5];
    const float* Wqkv     = (const float*)d_in[6];
    const float* Wo       = (const float*)d_in[7];
    const float* Wg       = (const float*)d_in[8];
    const float* gate_bias= (const float*)d_in[9];
    const float* Wgu      = (const float*)d_in[10];
    const float* Wd       = (const float*)d_in[11];
    const float* Wgu_sh   = (const float*)d_in[12];
    const float* Wd_sh    = (const float*)d_in[13];
    const int*   positions= (const int*)d_in[14];
    float* out = (float*)d_out;

    float *p_res1, *p_qkv, *p_h, *p_x2, *p_gu, *p_y, *p_gus, *p_shared;
    bf16 *p_xhi, *p_xlo, *p_x2hi, *p_x2lo, *p_aohi, *p_aolo;
    bf16 *p_acthi, *p_actlo, *p_actshi, *p_actslo;
    bf16 *p_wqkvhi, *p_wqkvlo, *p_wohi, *p_wolo, *p_wguhi, *p_wgulo;
    bf16 *p_wdhi, *p_wdlo, *p_wgushi, *p_wguslo, *p_wdshi, *p_wdslo;

    cudaGetSymbolAddress((void**)&p_res1,  g_res1);
    cudaGetSymbolAddress((void**)&p_qkv,   g_qkv);
    cudaGetSymbolAddress((void**)&p_h,     g_h);
    cudaGetSymbolAddress((void**)&p_x2,    g_x2);
    cudaGetSymbolAddress((void**)&p_gu,    g_gu);
    cudaGetSymbolAddress((void**)&p_y,     g_y);
    cudaGetSymbolAddress((void**)&p_gus,   g_gus);
    cudaGetSymbolAddress((void**)&p_shared,g_shared);
    cudaGetSymbolAddress((void**)&p_xhi,   g_xhi);
    cudaGetSymbolAddress((void**)&p_xlo,   g_xlo);
    cudaGetSymbolAddress((void**)&p_x2hi,  g_x2hi);
    cudaGetSymbolAddress((void**)&p_x2lo,  g_x2lo);
    cudaGetSymbolAddress((void**)&p_aohi,  g_aohi);
    cudaGetSymbolAddress((void**)&p_aolo,  g_aolo);
    cudaGetSymbolAddress((void**)&p_acthi, g_acthi);
    cudaGetSymbolAddress((void**)&p_actlo, g_actlo);
    cudaGetSymbolAddress((void**)&p_actshi,g_actshi);
    cudaGetSymbolAddress((void**)&p_actslo,g_actslo);
    cudaGetSymbolAddress((void**)&p_wqkvhi,g_wqkvhi);
    cudaGetSymbolAddress((void**)&p_wqkvlo,g_wqkvlo);
    cudaGetSymbolAddress((void**)&p_wohi,  g_wohi);
    cudaGetSymbolAddress((void**)&p_wolo,  g_wolo);
    cudaGetSymbolAddress((void**)&p_wguhi, g_wguhi);
    cudaGetSymbolAddress((void**)&p_wgulo, g_wgulo);
    cudaGetSymbolAddress((void**)&p_wdhi,  g_wdhi);
    cudaGetSymbolAddress((void**)&p_wdlo,  g_wdlo);
    cudaGetSymbolAddress((void**)&p_wgushi,g_wgushi);
    cudaGetSymbolAddress((void**)&p_wguslo,g_wguslo);
    cudaGetSymbolAddress((void**)&p_wdshi, g_wdshi);
    cudaGetSymbolAddress((void**)&p_wdslo, g_wdslo);

    cudaFuncSetAttribute(tc_gemm, cudaFuncAttributeMaxDynamicSharedMemorySize, GSM_TOTAL);
    cudaFuncSetAttribute(tc_attn, cudaFuncAttributeMaxDynamicSharedMemorySize, ASM_TOTAL);

    dim3 wblk(32, 8);

    // 1. residual1 = hidden + residual ; x = rms(...) -> bf16 split only
    add_rmsnorm_kernel<<<T, 256>>>(hidden, residual, p_res1, in_ln_w, nullptr, p_xhi, p_xlo);

    // 2. qkv = x @ Wqkv
    wsplitT<<<dim3(QKVW/32, H/32, 1), wblk>>>(Wqkv, p_wqkvhi, p_wqkvlo, H, QKVW);
    tc_gemm<<<dim3(QKVW/128, T/128), 256, GSM_TOTAL>>>(p_xhi, p_xlo, p_wqkvhi, p_wqkvlo,
                                                       p_qkv, QKVW, H, 0, 0);

    // 3. q/k rmsnorm + rope (writes hi/lo directly); split V columns
    qknorm_rope_kernel<<<(T*(NH+NKV))/8, 256>>>(q_norm_w, k_norm_w, positions);
    vsplit_kernel<<<T, 64>>>();

    // 4. attention (tensor cores; epilogue writes ao hi/lo)
    tc_attn<<<dim3(T/128, NH), 256, ASM_TOTAL>>>();

    // 5. h = attno @ Wo ; residual2 -> out ; x2 = rms(residual2)
    wsplitT<<<dim3(H/32, H/32, 1), wblk>>>(Wo, p_wohi, p_wolo, H, H);
    tc_gemm<<<dim3(H/128, T/128), 256, GSM_TOTAL>>>(p_aohi, p_aolo, p_wohi, p_wolo,
                                                    p_h, H, H, 0, 0);
    float* out_res = out + (size_t)T*H;
    add_rmsnorm_kernel<<<T, 256>>>(p_h, p_res1, out_res, post_ln_w, p_x2, p_x2hi, p_x2lo);

    // 6. router + dispatch
    zero_kernel<<<1, 32>>>();
    router_kernel<<<T, 32>>>(Wg, gate_bias);
    scan_kernel<<<1, 1>>>();
    scatter_kernel<<<(T + 255)/256, 256>>>();

    // 7. routed experts
    wsplitT<<<dim3(2*IM/32, H/32, E), wblk>>>(Wgu, p_wguhi, p_wgulo, H, 2*IM);
    tc_gemm<<<dim3(2*IM/128, NSLOT/128, E), 256, GSM_TOTAL>>>(p_x2hi, p_x2lo, p_wguhi, p_wgulo,
                                                              p_gu, 2*IM, H, 1, 1);
    silu_split<<<(NSLOT*IM + 255)/256, 256>>>(p_gu, p_acthi, p_actlo, NSLOT*IM);
    wsplitT<<<dim3(H/32, IM/32, E), wblk>>>(Wd, p_wdhi, p_wdlo, IM, H);
    tc_gemm<<<dim3(H/128, NSLOT/128, E), 256, GSM_TOTAL>>>(p_acthi, p_actlo, p_wdhi, p_wdlo,
                                                           p_y, H, IM, 1, 0);

    // 8. shared expert
    wsplitT<<<dim3(2*IM/32, H/32, 1), wblk>>>(Wgu_sh, p_wgushi, p_wguslo, H, 2*IM);
    tc_gemm<<<dim3(2*IM/128, T/128), 256, GSM_TOTAL>>>(p_x2hi, p_x2lo, p_wgushi, p_wguslo,
                                                       p_gus, 2*IM, H, 0, 0);
    silu_split<<<(T*IM + 255)/256, 256>>>(p_gus, p_actshi, p_actslo, T*IM);
    wsplitT<<<dim3(H/32, IM/32, 1), wblk>>>(Wd_sh, p_wdshi, p_wdslo, IM, H);
    tc_gemm<<<dim3(H/128, T/128), 256, GSM_TOTAL>>>(p_actshi, p_actslo, p_wdshi, p_wdslo,
                                                    p_shared, H, IM, 0, 0);

    // 9. combine
    combine_kernel<<<T, 256>>>(out);
}